// round 8
// baseline (speedup 1.0000x reference)
#include <cuda_runtime.h>
#include <cstdint>

// Problem constants (fixed shapes)
#define NMAX 50000
#define EMAX 800000
#define FDIM 128      // H*C
#define HEADS4 4

// ---------------- scratch (device globals; no allocation allowed) ----------
__device__ float g_lin [NMAX * FDIM];   // GEMM output (pre-aggregation h)
__device__ float g_feat[NMAX * FDIM];   // activated features / layer IO
__device__ float g_als [NMAX * HEADS4]; // per-node src logits
__device__ float g_ald [NMAX * HEADS4]; // per-node dst logits
__device__ int   g_counts[NMAX];
__device__ int   g_indptr[NMAX + 1];
__device__ int   g_cursor[NMAX];
__device__ int   g_csr   [EMAX];        // src node per CSR-slot (grouped by dst)
__device__ int   g_scanbuf[NMAX];       // per-block exclusive scan
__device__ int   g_blocksum[64];        // block totals -> block offsets
__device__ int   g_is64;

static inline int cdiv(int a, int b) { return (a + b - 1) / b; }

// ------------- init: zero counts + dtype probe (int64 vs int32) ------------
// Values are in [0, 50000): if stored as int64, every odd 32-bit word is 0.
__global__ void init_kernel(const unsigned int* __restrict__ w, int n) {
    int i = blockIdx.x * blockDim.x + threadIdx.x;
    if (i < n) g_counts[i] = 0;
    if (blockIdx.x == 0) {
        __shared__ int any;
        if (threadIdx.x == 0) any = 0;
        __syncthreads();
        int acc = 0;
        for (int j = threadIdx.x; j < 2048; j += blockDim.x) acc |= (int)w[2 * j + 1];
        atomicOr(&any, acc);
        __syncthreads();
        if (threadIdx.x == 0) g_is64 = (any == 0) ? 1 : 0;
    }
}

__global__ void count_dst_kernel(const void* __restrict__ ei, int E) {
    int i = blockIdx.x * blockDim.x + threadIdx.x;
    if (i >= E) return;
    int d = g_is64 ? (int)((const long long*)ei)[(size_t)E + i]
                   : ((const int*)ei)[E + i];
    atomicAdd(&g_counts[d], 1);
}

// --- multi-block scan, stage 1: per-block (1024 elems) exclusive scan ------
__global__ void __launch_bounds__(1024) scan1_kernel(int n) {
    __shared__ int warpsum[32];
    int i = blockIdx.x * 1024 + threadIdx.x;
    int lane = threadIdx.x & 31, w = threadIdx.x >> 5;
    int v = (i < n) ? g_counts[i] : 0;
    int x = v;
#pragma unroll
    for (int d = 1; d < 32; d <<= 1) {
        int t = __shfl_up_sync(0xffffffffu, x, d);
        if (lane >= d) x += t;
    }
    if (lane == 31) warpsum[w] = x;
    __syncthreads();
    if (w == 0) {
        int s = warpsum[lane];
#pragma unroll
        for (int d = 1; d < 32; d <<= 1) {
            int t = __shfl_up_sync(0xffffffffu, s, d);
            if (lane >= d) s += t;
        }
        warpsum[lane] = s;
    }
    __syncthreads();
    int incl = x + (w > 0 ? warpsum[w - 1] : 0);
    if (i < n) g_scanbuf[i] = incl - v;                 // exclusive within block
    if (threadIdx.x == 1023) g_blocksum[blockIdx.x] = incl;
}

// --- stage 2: scan the (<=64) block sums; also writes total -> indptr[n] ---
__global__ void scan2_kernel(int nb, int n) {
    __shared__ int sh[64];
    int t = threadIdx.x;
    int v = (t < nb) ? g_blocksum[t] : 0;
    sh[t] = v;
    __syncthreads();
#pragma unroll
    for (int d = 1; d < 64; d <<= 1) {
        int x = (t >= d) ? sh[t - d] : 0;
        __syncthreads();
        sh[t] += x;
        __syncthreads();
    }
    if (t < nb) g_blocksum[t] = sh[t] - v;              // exclusive block offset
    if (t == 63) g_indptr[n] = sh[63];
}

// --- stage 3: combine -> indptr / cursor -----------------------------------
__global__ void scan3_kernel(int n) {
    int i = blockIdx.x * blockDim.x + threadIdx.x;
    if (i >= n) return;
    int off = g_blocksum[i >> 10] + g_scanbuf[i];
    g_indptr[i] = off;
    g_cursor[i] = off;
}

__global__ void scatter_kernel(const void* __restrict__ ei, int E) {
    int i = blockIdx.x * blockDim.x + threadIdx.x;
    if (i >= E) return;
    int s, d;
    if (g_is64) {
        s = (int)((const long long*)ei)[i];
        d = (int)((const long long*)ei)[(size_t)E + i];
    } else {
        s = ((const int*)ei)[i];
        d = ((const int*)ei)[E + i];
    }
    int pos = atomicAdd(&g_cursor[d], 1);
    g_csr[pos] = s;
}

// ---------------- GEMM + fused attention logits ----------------------------
// C[M x BN] = A[M x K] @ B[K x BN]; BN == actual N == ldb.
// Double-buffered smem, 1 sync/tile. Epilogue computes
//   g_als[m][h] = <C[m, h*32:(h+1)*32], aS[h]>, g_ald likewise,
// exploiting that head h owns columns [h*32, h*32+32) and aS/aD flatten to
// a [BN] vector aligned with columns. Per-thread partials are reduced over
// the 8 lanes sharing the same rows+head via shfl_xor.
template <int BM, int BN, int TM, int TN, int HEADS>
__global__ void __launch_bounds__(256) gemm_logits_kernel(
    const float* __restrict__ A, const float* __restrict__ B,
    const float* __restrict__ aS, const float* __restrict__ aD,
    float* __restrict__ C, int M, int K)
{
    constexpr int BK = 16;
    constexpr int TX = BN / TN;
    constexpr int TY = BM / TM;
    static_assert(TX * TY == 256, "256 threads");
    static_assert(TM % 4 == 0 && TN % 4 == 0, "float4 fragments");
    static_assert(TX % 8 == 0, "8-lane logit reduce needs TX multiple of 8");
    constexpr int AG = TM / 4;
    constexpr int NG = TN / 4;
    constexpr int GS = BN / NG;
    constexpr int APAD = 4;
    constexpr int AE = BM * BK / 256;
    constexpr int BE = BK * BN / 256;

    __shared__ float As[2][BK][BM + APAD];
    __shared__ float Bs[2][BK][BN];

    int tid = threadIdx.x;
    int tx = tid % TX, ty = tid / TX;
    int m0 = blockIdx.x * BM;

    float acc[TM][TN];
#pragma unroll
    for (int i = 0; i < TM; i++)
#pragma unroll
        for (int j = 0; j < TN; j++) acc[i][j] = 0.f;

    float ra[AE], rb[BE];
    // prologue: tile 0 -> regs -> smem buf 0
#pragma unroll
    for (int i = 0; i < AE; i++) {
        int idx = tid + i * 256;
        int am = idx / BK, ak = idx % BK;
        int gm = m0 + am;
        ra[i] = (gm < M) ? A[(size_t)gm * K + ak] : 0.f;
    }
#pragma unroll
    for (int i = 0; i < BE; i++) {
        int idx = tid + i * 256;
        int bk = idx / BN, bn = idx % BN;
        rb[i] = B[(size_t)bk * BN + bn];
    }
#pragma unroll
    for (int i = 0; i < AE; i++) {
        int idx = tid + i * 256;
        As[0][idx % BK][idx / BK] = ra[i];
    }
#pragma unroll
    for (int i = 0; i < BE; i++) {
        int idx = tid + i * 256;
        Bs[0][idx / BN][idx % BN] = rb[i];
    }
    __syncthreads();

    int T = K / BK;
    for (int t = 0; t < T; t++) {
        int p = t & 1;
        if (t + 1 < T) {
            int k0 = (t + 1) * BK;
#pragma unroll
            for (int i = 0; i < AE; i++) {
                int idx = tid + i * 256;
                int am = idx / BK, ak = idx % BK;
                int gm = m0 + am;
                ra[i] = (gm < M) ? A[(size_t)gm * K + k0 + ak] : 0.f;
            }
#pragma unroll
            for (int i = 0; i < BE; i++) {
                int idx = tid + i * 256;
                int bk = idx / BN, bn = idx % BN;
                rb[i] = B[(size_t)(k0 + bk) * BN + bn];
            }
        }
#pragma unroll
        for (int k = 0; k < BK; k++) {
            float a[TM];
#pragma unroll
            for (int g = 0; g < AG; g++) {
                float4 av = *(const float4*)&As[p][k][ty * TM + g * 4];
                a[g * 4 + 0] = av.x; a[g * 4 + 1] = av.y;
                a[g * 4 + 2] = av.z; a[g * 4 + 3] = av.w;
            }
            float b[TN];
#pragma unroll
            for (int g = 0; g < NG; g++) {
                float4 bv = *(const float4*)&Bs[p][k][g * GS + tx * 4];
                b[g * 4 + 0] = bv.x; b[g * 4 + 1] = bv.y;
                b[g * 4 + 2] = bv.z; b[g * 4 + 3] = bv.w;
            }
#pragma unroll
            for (int i = 0; i < TM; i++)
#pragma unroll
                for (int j = 0; j < TN; j++) acc[i][j] += a[i] * b[j];
        }
        if (t + 1 < T) {
            int q = p ^ 1;
#pragma unroll
            for (int i = 0; i < AE; i++) {
                int idx = tid + i * 256;
                As[q][idx % BK][idx / BK] = ra[i];
            }
#pragma unroll
            for (int i = 0; i < BE; i++) {
                int idx = tid + i * 256;
                Bs[q][idx / BN][idx % BN] = rb[i];
            }
        }
        __syncthreads();
    }

    // epilogue: C store + fused logits
#pragma unroll
    for (int i = 0; i < TM; i++) {
        int gm = m0 + ty * TM + i;
#pragma unroll
        for (int g = 0; g < NG; g++) {
            int colbase = g * GS + tx * 4;
            float4 v = make_float4(acc[i][g * 4 + 0], acc[i][g * 4 + 1],
                                   acc[i][g * 4 + 2], acc[i][g * 4 + 3]);
            if (gm < M)
                *(float4*)&C[(size_t)gm * BN + colbase] = v;
            float pS = v.x * aS[colbase]     + v.y * aS[colbase + 1]
                     + v.z * aS[colbase + 2] + v.w * aS[colbase + 3];
            float pD = v.x * aD[colbase]     + v.y * aD[colbase + 1]
                     + v.z * aD[colbase + 2] + v.w * aD[colbase + 3];
#pragma unroll
            for (int off = 4; off; off >>= 1) {
                pS += __shfl_xor_sync(0xffffffffu, pS, off);
                pD += __shfl_xor_sync(0xffffffffu, pD, off);
            }
            if ((tx & 7) == 0 && gm < M) {
                int head = colbase >> 5;        // CH = 32 columns per head
                g_als[gm * HEADS + head] = pS;
                g_ald[gm * HEADS + head] = pD;
            }
        }
    }
}

// ---------------- GAT aggregation: one warp per destination node -----------
// Pass 1: online softmax (max + denom in one sweep). Pass 2: weighted
// aggregate, 2-way unrolled. Self-loop handled analytically (lane 0 seeds it).
template <int HEADS, int CH, bool ACT, bool FUSE_HEAD>
__global__ void __launch_bounds__(256) gat_agg_kernel(
    const float* __restrict__ h, const float* __restrict__ bias,
    const float* __restrict__ Wc, const float* __restrict__ bc,
    float* __restrict__ out, int n)
{
    constexpr int F = HEADS * CH;
    constexpr int CL = F / 32;                 // channels per lane
    int warp = (blockIdx.x * blockDim.x + threadIdx.x) >> 5;
    int lane = threadIdx.x & 31;
    if (warp >= n) return;

    int start = g_indptr[warp], end = g_indptr[warp + 1];

    float aldv[HEADS], self_e[HEADS], m[HEADS], den[HEADS];
    if constexpr (HEADS == 4) {
        float4 t = *(const float4*)&g_ald[warp * 4];
        aldv[0] = t.x; aldv[1] = t.y; aldv[2] = t.z; aldv[3] = t.w;
        float4 u = *(const float4*)&g_als[warp * 4];
        float sv[4] = {u.x, u.y, u.z, u.w};
#pragma unroll
        for (int hh = 0; hh < 4; hh++) {
            float e = sv[hh] + aldv[hh];
            self_e[hh] = e > 0.f ? e : 0.2f * e;
        }
    } else {
        aldv[0] = g_ald[warp];
        float e = g_als[warp] + aldv[0];
        self_e[0] = e > 0.f ? e : 0.2f * e;
    }
#pragma unroll
    for (int hh = 0; hh < HEADS; hh++) {
        m[hh]   = (lane == 0) ? self_e[hh] : -1e30f;
        den[hh] = (lane == 0) ? 1.f : 0.f;
    }

    // pass 1: online softmax over this node's in-edges
    for (int eb = start; eb < end; eb += 32) {
        int e = eb + lane;
        if (e < end) {
            int s = g_csr[e];
            if constexpr (HEADS == 4) {
                float4 u = *(const float4*)&g_als[s * 4];
                float sv[4] = {u.x, u.y, u.z, u.w};
#pragma unroll
                for (int hh = 0; hh < 4; hh++) {
                    float x = sv[hh] + aldv[hh];
                    x = x > 0.f ? x : 0.2f * x;
                    float mn = fmaxf(m[hh], x);
                    den[hh] = den[hh] * __expf(m[hh] - mn) + __expf(x - mn);
                    m[hh] = mn;
                }
            } else {
                float x = g_als[s] + aldv[0];
                x = x > 0.f ? x : 0.2f * x;
                float mn = fmaxf(m[0], x);
                den[0] = den[0] * __expf(m[0] - mn) + __expf(x - mn);
                m[0] = mn;
            }
        }
    }
#pragma unroll
    for (int hh = 0; hh < HEADS; hh++) {
        float M_ = m[hh];
#pragma unroll
        for (int off = 16; off; off >>= 1)
            M_ = fmaxf(M_, __shfl_xor_sync(0xffffffffu, M_, off));
        float d = den[hh] * __expf(m[hh] - M_);
#pragma unroll
        for (int off = 16; off; off >>= 1)
            d += __shfl_xor_sync(0xffffffffu, d, off);
        m[hh] = M_;
        den[hh] = 1.f / (d + 1e-16f);
    }

    // pass 2: aggregate. Lane owns channels [lane*CL, lane*CL+CL), one head.
    int myhead = (HEADS == 1) ? 0 : (lane >> 3);
    float mym = m[myhead], myden = den[myhead], mya = aldv[myhead];
    float acc[CL];
    {
        float alpha = __expf(self_e[myhead] - mym) * myden;
        if constexpr (CL == 4) {
            float4 hv = *(const float4*)&h[(size_t)warp * F + lane * 4];
            acc[0] = hv.x * alpha; acc[1] = hv.y * alpha;
            acc[2] = hv.z * alpha; acc[3] = hv.w * alpha;
        } else {
            acc[0] = h[(size_t)warp * F + lane] * alpha;
        }
    }
    int e = start;
    for (; e + 1 < end; e += 2) {
        int s0 = g_csr[e], s1 = g_csr[e + 1];
        float x0 = g_als[s0 * HEADS + myhead] + mya;
        float x1 = g_als[s1 * HEADS + myhead] + mya;
        x0 = x0 > 0.f ? x0 : 0.2f * x0;
        x1 = x1 > 0.f ? x1 : 0.2f * x1;
        float al0 = __expf(x0 - mym) * myden;
        float al1 = __expf(x1 - mym) * myden;
        if constexpr (CL == 4) {
            float4 h0 = *(const float4*)&h[(size_t)s0 * F + lane * 4];
            float4 h1 = *(const float4*)&h[(size_t)s1 * F + lane * 4];
            acc[0] += h0.x * al0 + h1.x * al1;
            acc[1] += h0.y * al0 + h1.y * al1;
            acc[2] += h0.z * al0 + h1.z * al1;
            acc[3] += h0.w * al0 + h1.w * al1;
        } else {
            acc[0] += h[(size_t)s0 * F + lane] * al0
                    + h[(size_t)s1 * F + lane] * al1;
        }
    }
    if (e < end) {
        int s0 = g_csr[e];
        float x0 = g_als[s0 * HEADS + myhead] + mya;
        x0 = x0 > 0.f ? x0 : 0.2f * x0;
        float al0 = __expf(x0 - mym) * myden;
        if constexpr (CL == 4) {
            float4 h0 = *(const float4*)&h[(size_t)s0 * F + lane * 4];
            acc[0] += h0.x * al0; acc[1] += h0.y * al0;
            acc[2] += h0.z * al0; acc[3] += h0.w * al0;
        } else {
            acc[0] += h[(size_t)s0 * F + lane] * al0;
        }
    }

    if constexpr (FUSE_HEAD) {
        // layer 3: write link embedding + classifier logits directly to out
        float v = acc[0] + bias[lane];
        out[(size_t)n * 2 + (size_t)warp * 32 + lane] = v;
        float p0 = v * Wc[lane * 2 + 0];
        float p1 = v * Wc[lane * 2 + 1];
#pragma unroll
        for (int off = 16; off; off >>= 1) {
            p0 += __shfl_xor_sync(0xffffffffu, p0, off);
            p1 += __shfl_xor_sync(0xffffffffu, p1, off);
        }
        if (lane == 0) {
            out[(size_t)warp * 2 + 0] = p0 + bc[0];
            out[(size_t)warp * 2 + 1] = p1 + bc[1];
        }
    } else {
#pragma unroll
        for (int j = 0; j < CL; j++) {
            int c = lane * CL + j;
            float v = acc[j] + bias[c];
            if (ACT) v = v > 0.f ? v : (__expf(v) - 1.f);
            out[(size_t)warp * F + c] = v;
        }
    }
}

// ---------------- launch ----------------------------------------------------
extern "C" void kernel_launch(void* const* d_in, const int* in_sizes, int n_in,
                              void* d_out, int out_size)
{
    const float*  x    = (const float*)d_in[0];
    const void*   ei   = d_in[1];
    const float*  W1   = (const float*)d_in[2];
    const float*  a1s  = (const float*)d_in[3];
    const float*  a1d  = (const float*)d_in[4];
    const float*  b1   = (const float*)d_in[5];
    const float*  W2   = (const float*)d_in[6];
    const float*  a2s  = (const float*)d_in[7];
    const float*  a2d  = (const float*)d_in[8];
    const float*  b2   = (const float*)d_in[9];
    const float*  W3   = (const float*)d_in[10];
    const float*  a3s  = (const float*)d_in[11];
    const float*  a3d  = (const float*)d_in[12];
    const float*  b3   = (const float*)d_in[13];
    const float*  Wc   = (const float*)d_in[14];
    const float*  bc   = (const float*)d_in[15];
    float* out = (float*)d_out;

    int N = in_sizes[0] / FDIM;     // 50000
    int E = in_sizes[1] / 2;        // 800000 (element count same for i32/i64)

    float *lin, *feat;
    cudaGetSymbolAddress((void**)&lin,  g_lin);
    cudaGetSymbolAddress((void**)&feat, g_feat);

    // --- CSR by destination (rebuilt every replay; deterministic work) ---
    init_kernel<<<cdiv(N, 256), 256>>>((const unsigned int*)ei, N);
    count_dst_kernel<<<cdiv(E, 256), 256>>>(ei, E);
    int nb = cdiv(N, 1024);
    scan1_kernel<<<nb, 1024>>>(N);
    scan2_kernel<<<1, 64>>>(nb, N);
    scan3_kernel<<<cdiv(N, 256), 256>>>(N);
    scatter_kernel<<<cdiv(E, 256), 256>>>(ei, E);

    // --- layer 1: x[128] -> 128, 4 heads, ELU ---
    gemm_logits_kernel<128, 128, 8, 8, 4><<<cdiv(N, 128), 256>>>(
        x, W1, a1s, a1d, lin, N, 128);
    gat_agg_kernel<4, 32, true, false><<<cdiv(N * 32, 256), 256>>>(
        lin, b1, nullptr, nullptr, feat, N);

    // --- layer 2: 128 -> 128, 4 heads, ELU ---
    gemm_logits_kernel<128, 128, 8, 8, 4><<<cdiv(N, 128), 256>>>(
        feat, W2, a2s, a2d, lin, N, 128);
    gat_agg_kernel<4, 32, true, false><<<cdiv(N * 32, 256), 256>>>(
        lin, b2, nullptr, nullptr, feat, N);

    // --- layer 3: 128 -> 32, 1 head, no activation; fused classifier head ---
    gemm_logits_kernel<128, 32, 4, 4, 1><<<cdiv(N, 128), 256>>>(
        feat, W3, a3s, a3d, lin, N, 128);
    gat_agg_kernel<1, 32, false, true><<<cdiv(N * 32, 256), 256>>>(
        lin, b3, Wc, bc, out, N);
}

// round 9
// speedup vs baseline: 1.4391x; 1.4391x over previous
#include <cuda_runtime.h>
#include <cstdint>

// Problem constants (fixed shapes)
#define NMAX 50000
#define EMAX 800000
#define FDIM 128      // H*C
#define HEADS4 4

// ---------------- scratch (device globals; no allocation allowed) ----------
__device__ float g_lin [NMAX * FDIM];   // GEMM output (pre-aggregation h)
__device__ float g_feat[NMAX * FDIM];   // activated features / layer IO
__device__ float g_als [NMAX * HEADS4]; // per-node src logits
__device__ float g_ald [NMAX * HEADS4]; // per-node dst logits
__device__ int   g_counts[NMAX];
__device__ int   g_indptr[NMAX + 1];
__device__ int   g_cursor[NMAX];
__device__ int   g_csr   [EMAX];        // src node per CSR-slot (grouped by dst)
__device__ int   g_scanbuf[NMAX];       // per-block exclusive scan
__device__ int   g_blocksum[64];        // block totals -> block offsets
__device__ int   g_is64;

static inline int cdiv(int a, int b) { return (a + b - 1) / b; }

// ------------- init: zero counts + dtype probe (int64 vs int32) ------------
// Values are in [0, 50000): if stored as int64, every odd 32-bit word is 0.
__global__ void init_kernel(const unsigned int* __restrict__ w, int n) {
    int i = blockIdx.x * blockDim.x + threadIdx.x;
    if (i < n) g_counts[i] = 0;
    if (blockIdx.x == 0) {
        __shared__ int any;
        if (threadIdx.x == 0) any = 0;
        __syncthreads();
        int acc = 0;
        for (int j = threadIdx.x; j < 2048; j += blockDim.x) acc |= (int)w[2 * j + 1];
        atomicOr(&any, acc);
        __syncthreads();
        if (threadIdx.x == 0) g_is64 = (any == 0) ? 1 : 0;
    }
}

__global__ void count_dst_kernel(const void* __restrict__ ei, int E) {
    int i = blockIdx.x * blockDim.x + threadIdx.x;
    if (i >= E) return;
    int d = g_is64 ? (int)((const long long*)ei)[(size_t)E + i]
                   : ((const int*)ei)[E + i];
    atomicAdd(&g_counts[d], 1);
}

// --- multi-block scan, stage 1: per-block (1024 elems) exclusive scan ------
__global__ void __launch_bounds__(1024) scan1_kernel(int n) {
    __shared__ int warpsum[32];
    int i = blockIdx.x * 1024 + threadIdx.x;
    int lane = threadIdx.x & 31, w = threadIdx.x >> 5;
    int v = (i < n) ? g_counts[i] : 0;
    int x = v;
#pragma unroll
    for (int d = 1; d < 32; d <<= 1) {
        int t = __shfl_up_sync(0xffffffffu, x, d);
        if (lane >= d) x += t;
    }
    if (lane == 31) warpsum[w] = x;
    __syncthreads();
    if (w == 0) {
        int s = warpsum[lane];
#pragma unroll
        for (int d = 1; d < 32; d <<= 1) {
            int t = __shfl_up_sync(0xffffffffu, s, d);
            if (lane >= d) s += t;
        }
        warpsum[lane] = s;
    }
    __syncthreads();
    int incl = x + (w > 0 ? warpsum[w - 1] : 0);
    if (i < n) g_scanbuf[i] = incl - v;                 // exclusive within block
    if (threadIdx.x == 1023) g_blocksum[blockIdx.x] = incl;
}

// --- stage 2: scan the (<=64) block sums; also writes total -> indptr[n] ---
__global__ void scan2_kernel(int nb, int n) {
    __shared__ int sh[64];
    int t = threadIdx.x;
    int v = (t < nb) ? g_blocksum[t] : 0;
    sh[t] = v;
    __syncthreads();
#pragma unroll
    for (int d = 1; d < 64; d <<= 1) {
        int x = (t >= d) ? sh[t - d] : 0;
        __syncthreads();
        sh[t] += x;
        __syncthreads();
    }
    if (t < nb) g_blocksum[t] = sh[t] - v;              // exclusive block offset
    if (t == 63) g_indptr[n] = sh[63];
}

// --- stage 3: combine -> indptr / cursor -----------------------------------
__global__ void scan3_kernel(int n) {
    int i = blockIdx.x * blockDim.x + threadIdx.x;
    if (i >= n) return;
    int off = g_blocksum[i >> 10] + g_scanbuf[i];
    g_indptr[i] = off;
    g_cursor[i] = off;
}

__global__ void scatter_kernel(const void* __restrict__ ei, int E) {
    int i = blockIdx.x * blockDim.x + threadIdx.x;
    if (i >= E) return;
    int s, d;
    if (g_is64) {
        s = (int)((const long long*)ei)[i];
        d = (int)((const long long*)ei)[(size_t)E + i];
    } else {
        s = ((const int*)ei)[i];
        d = ((const int*)ei)[E + i];
    }
    int pos = atomicAdd(&g_cursor[d], 1);
    g_csr[pos] = s;
}

// ---------------- GEMM + fused attention logits ----------------------------
// C[M x BN] = A[M x K] @ B[K x BN]; BN == actual N == ldb. Single-buffered
// (round-7 proven inner loop). Epilogue additionally computes
//   g_als[m][h] = <C[m, h*32:(h+1)*32], aS flattened>, g_ald likewise:
// head h owns columns [h*32, h*32+32), so per-thread partial dots on the
// register-resident acc reduce over the 8 lanes sharing rows+head via shfl.
template <int BM, int BN, int TM, int TN, int HEADS>
__global__ void __launch_bounds__(256) gemm_logits_kernel(
    const float* __restrict__ A, const float* __restrict__ B,
    const float* __restrict__ aS, const float* __restrict__ aD,
    float* __restrict__ C, int M, int K)
{
    constexpr int BK = 16;
    constexpr int TX = BN / TN;
    constexpr int TY = BM / TM;
    static_assert(TX * TY == 256, "256 threads");
    static_assert(TM % 4 == 0 && TN % 4 == 0, "float4 fragments");
    static_assert(TX % 8 == 0, "8-lane logit reduce needs TX multiple of 8");
    constexpr int AG = TM / 4;             // float4 groups per thread in M
    constexpr int NG = TN / 4;             // float4 groups per thread in N
    constexpr int GS = BN / NG;            // group stride in columns
    constexpr int APAD = 4;

    __shared__ float As[BK][BM + APAD];
    __shared__ float Bs[BK][BN];

    int tid = threadIdx.x;
    int tx = tid % TX, ty = tid / TX;
    int m0 = blockIdx.x * BM;

    float acc[TM][TN];
#pragma unroll
    for (int i = 0; i < TM; i++)
#pragma unroll
        for (int j = 0; j < TN; j++) acc[i][j] = 0.f;

    for (int k0 = 0; k0 < K; k0 += BK) {
        constexpr int AE = BM * BK / 256;
#pragma unroll
        for (int i = 0; i < AE; i++) {
            int idx = tid + i * 256;
            int am = idx / BK, ak = idx % BK;
            int gm = m0 + am;
            As[ak][am] = (gm < M) ? A[(size_t)gm * K + k0 + ak] : 0.f;
        }
        constexpr int BE = BK * BN / 256;
#pragma unroll
        for (int i = 0; i < BE; i++) {
            int idx = tid + i * 256;
            int bk = idx / BN, bn = idx % BN;
            Bs[bk][bn] = B[(size_t)(k0 + bk) * BN + bn];
        }
        __syncthreads();
#pragma unroll
        for (int k = 0; k < BK; k++) {
            float a[TM];
#pragma unroll
            for (int g = 0; g < AG; g++) {
                float4 av = *(const float4*)&As[k][ty * TM + g * 4];
                a[g * 4 + 0] = av.x; a[g * 4 + 1] = av.y;
                a[g * 4 + 2] = av.z; a[g * 4 + 3] = av.w;
            }
            float b[TN];
#pragma unroll
            for (int g = 0; g < NG; g++) {
                float4 bv = *(const float4*)&Bs[k][g * GS + tx * 4];
                b[g * 4 + 0] = bv.x; b[g * 4 + 1] = bv.y;
                b[g * 4 + 2] = bv.z; b[g * 4 + 3] = bv.w;
            }
#pragma unroll
            for (int i = 0; i < TM; i++)
#pragma unroll
                for (int j = 0; j < TN; j++) acc[i][j] += a[i] * b[j];
        }
        __syncthreads();
    }

    // epilogue: C store + fused logits
#pragma unroll
    for (int i = 0; i < TM; i++) {
        int gm = m0 + ty * TM + i;
#pragma unroll
        for (int g = 0; g < NG; g++) {
            int colbase = g * GS + tx * 4;
            float4 v = make_float4(acc[i][g * 4 + 0], acc[i][g * 4 + 1],
                                   acc[i][g * 4 + 2], acc[i][g * 4 + 3]);
            if (gm < M)
                *(float4*)&C[(size_t)gm * BN + colbase] = v;
            float pS = v.x * aS[colbase]     + v.y * aS[colbase + 1]
                     + v.z * aS[colbase + 2] + v.w * aS[colbase + 3];
            float pD = v.x * aD[colbase]     + v.y * aD[colbase + 1]
                     + v.z * aD[colbase + 2] + v.w * aD[colbase + 3];
#pragma unroll
            for (int off = 4; off; off >>= 1) {
                pS += __shfl_xor_sync(0xffffffffu, pS, off);
                pD += __shfl_xor_sync(0xffffffffu, pD, off);
            }
            if ((tx & 7) == 0 && gm < M) {
                int head = colbase >> 5;        // CH = 32 columns per head
                g_als[gm * HEADS + head] = pS;
                g_ald[gm * HEADS + head] = pD;
            }
        }
    }
}

// ---------------- GAT aggregation: one warp per destination node -----------
// Round-7 proven structure: pass A max, pass B denom, pass C aggregate with
// prefetch pipeline. Self-loop handled analytically. Optional fused classifier.
template <int HEADS, int CH, bool ACT, bool FUSE_HEAD>
__global__ void __launch_bounds__(256) gat_agg_kernel(
    const float* __restrict__ h, const float* __restrict__ bias,
    const float* __restrict__ Wc, const float* __restrict__ bc,
    float* __restrict__ out, int n)
{
    constexpr int F = HEADS * CH;
    constexpr int CL = F / 32;                 // channels per lane
    int warp = (blockIdx.x * blockDim.x + threadIdx.x) >> 5;
    int lane = threadIdx.x & 31;
    if (warp >= n) return;

    int start = g_indptr[warp], end = g_indptr[warp + 1];

    float aldv[HEADS], self_e[HEADS], m[HEADS];
    if constexpr (HEADS == 4) {
        float4 t = *(const float4*)&g_ald[warp * 4];
        aldv[0] = t.x; aldv[1] = t.y; aldv[2] = t.z; aldv[3] = t.w;
        float4 u = *(const float4*)&g_als[warp * 4];
        float sv[4] = {u.x, u.y, u.z, u.w};
#pragma unroll
        for (int hh = 0; hh < 4; hh++) {
            float e = sv[hh] + aldv[hh];
            e = e > 0.f ? e : 0.2f * e;
            self_e[hh] = e; m[hh] = e;
        }
    } else {
        aldv[0] = g_ald[warp];
        float e = g_als[warp] + aldv[0];
        e = e > 0.f ? e : 0.2f * e;
        self_e[0] = e; m[0] = e;
    }

    // pass A: max
    for (int eb = start; eb < end; eb += 32) {
        int e = eb + lane;
        if (e < end) {
            int s = g_csr[e];
            if constexpr (HEADS == 4) {
                float4 u = *(const float4*)&g_als[s * 4];
                float sv[4] = {u.x, u.y, u.z, u.w};
#pragma unroll
                for (int hh = 0; hh < 4; hh++) {
                    float x = sv[hh] + aldv[hh];
                    x = x > 0.f ? x : 0.2f * x;
                    m[hh] = fmaxf(m[hh], x);
                }
            } else {
                float x = g_als[s] + aldv[0];
                x = x > 0.f ? x : 0.2f * x;
                m[0] = fmaxf(m[0], x);
            }
        }
    }
#pragma unroll
    for (int hh = 0; hh < HEADS; hh++)
#pragma unroll
        for (int off = 16; off; off >>= 1)
            m[hh] = fmaxf(m[hh], __shfl_xor_sync(0xffffffffu, m[hh], off));

    // pass B: denom
    float den[HEADS];
#pragma unroll
    for (int hh = 0; hh < HEADS; hh++) den[hh] = 0.f;
    for (int eb = start; eb < end; eb += 32) {
        int e = eb + lane;
        if (e < end) {
            int s = g_csr[e];
            if constexpr (HEADS == 4) {
                float4 u = *(const float4*)&g_als[s * 4];
                float sv[4] = {u.x, u.y, u.z, u.w};
#pragma unroll
                for (int hh = 0; hh < 4; hh++) {
                    float x = sv[hh] + aldv[hh];
                    x = x > 0.f ? x : 0.2f * x;
                    den[hh] += __expf(x - m[hh]);
                }
            } else {
                float x = g_als[s] + aldv[0];
                x = x > 0.f ? x : 0.2f * x;
                den[0] += __expf(x - m[0]);
            }
        }
    }
#pragma unroll
    for (int hh = 0; hh < HEADS; hh++) {
#pragma unroll
        for (int off = 16; off; off >>= 1)
            den[hh] += __shfl_xor_sync(0xffffffffu, den[hh], off);
        den[hh] += __expf(self_e[hh] - m[hh]);
        den[hh] = 1.f / (den[hh] + 1e-16f);
    }

    // pass C: aggregate. Lane owns channels [lane*CL, lane*CL+CL), one head.
    int myhead = (HEADS == 1) ? 0 : (lane >> 3);
    float mym = m[myhead], myden = den[myhead], mya = aldv[myhead];
    float acc[CL];
    {
        float alpha = __expf(self_e[myhead] - mym) * myden;
        if constexpr (CL == 4) {
            float4 hv = *(const float4*)&h[(size_t)warp * F + lane * 4];
            acc[0] = hv.x * alpha; acc[1] = hv.y * alpha;
            acc[2] = hv.z * alpha; acc[3] = hv.w * alpha;
        } else {
            acc[0] = h[(size_t)warp * F + lane] * alpha;
        }
    }
    int s = (start < end) ? g_csr[start] : 0;   // prefetch pipeline
    for (int e = start; e < end; e++) {
        int snext = (e + 1 < end) ? g_csr[e + 1] : 0;
        float x = g_als[s * HEADS + myhead] + mya;
        x = x > 0.f ? x : 0.2f * x;
        float alpha = __expf(x - mym) * myden;
        if constexpr (CL == 4) {
            float4 hv = *(const float4*)&h[(size_t)s * F + lane * 4];
            acc[0] += hv.x * alpha; acc[1] += hv.y * alpha;
            acc[2] += hv.z * alpha; acc[3] += hv.w * alpha;
        } else {
            acc[0] += h[(size_t)s * F + lane] * alpha;
        }
        s = snext;
    }

    if constexpr (FUSE_HEAD) {
        // layer 3: write link embedding + classifier logits directly to out
        float v = acc[0] + bias[lane];
        out[(size_t)n * 2 + (size_t)warp * 32 + lane] = v;
        float p0 = v * Wc[lane * 2 + 0];
        float p1 = v * Wc[lane * 2 + 1];
#pragma unroll
        for (int off = 16; off; off >>= 1) {
            p0 += __shfl_xor_sync(0xffffffffu, p0, off);
            p1 += __shfl_xor_sync(0xffffffffu, p1, off);
        }
        if (lane == 0) {
            out[(size_t)warp * 2 + 0] = p0 + bc[0];
            out[(size_t)warp * 2 + 1] = p1 + bc[1];
        }
    } else {
#pragma unroll
        for (int j = 0; j < CL; j++) {
            int c = lane * CL + j;
            float v = acc[j] + bias[c];
            if (ACT) v = v > 0.f ? v : (__expf(v) - 1.f);
            out[(size_t)warp * F + c] = v;
        }
    }
}

// ---------------- launch ----------------------------------------------------
extern "C" void kernel_launch(void* const* d_in, const int* in_sizes, int n_in,
                              void* d_out, int out_size)
{
    const float*  x    = (const float*)d_in[0];
    const void*   ei   = d_in[1];
    const float*  W1   = (const float*)d_in[2];
    const float*  a1s  = (const float*)d_in[3];
    const float*  a1d  = (const float*)d_in[4];
    const float*  b1   = (const float*)d_in[5];
    const float*  W2   = (const float*)d_in[6];
    const float*  a2s  = (const float*)d_in[7];
    const float*  a2d  = (const float*)d_in[8];
    const float*  b2   = (const float*)d_in[9];
    const float*  W3   = (const float*)d_in[10];
    const float*  a3s  = (const float*)d_in[11];
    const float*  a3d  = (const float*)d_in[12];
    const float*  b3   = (const float*)d_in[13];
    const float*  Wc   = (const float*)d_in[14];
    const float*  bc   = (const float*)d_in[15];
    float* out = (float*)d_out;

    int N = in_sizes[0] / FDIM;     // 50000
    int E = in_sizes[1] / 2;        // 800000 (element count same for i32/i64)

    float *lin, *feat;
    cudaGetSymbolAddress((void**)&lin,  g_lin);
    cudaGetSymbolAddress((void**)&feat, g_feat);

    // --- CSR by destination (rebuilt every replay; deterministic work) ---
    init_kernel<<<cdiv(N, 256), 256>>>((const unsigned int*)ei, N);
    count_dst_kernel<<<cdiv(E, 256), 256>>>(ei, E);
    int nb = cdiv(N, 1024);
    scan1_kernel<<<nb, 1024>>>(N);
    scan2_kernel<<<1, 64>>>(nb, N);
    scan3_kernel<<<cdiv(N, 256), 256>>>(N);
    scatter_kernel<<<cdiv(E, 256), 256>>>(ei, E);

    // --- layer 1: x[128] -> 128, 4 heads, ELU ---
    gemm_logits_kernel<128, 128, 8, 8, 4><<<cdiv(N, 128), 256>>>(
        x, W1, a1s, a1d, lin, N, 128);
    gat_agg_kernel<4, 32, true, false><<<cdiv(N * 32, 256), 256>>>(
        lin, b1, nullptr, nullptr, feat, N);

    // --- layer 2: 128 -> 128, 4 heads, ELU ---
    gemm_logits_kernel<128, 128, 8, 8, 4><<<cdiv(N, 128), 256>>>(
        feat, W2, a2s, a2d, lin, N, 128);
    gat_agg_kernel<4, 32, true, false><<<cdiv(N * 32, 256), 256>>>(
        lin, b2, nullptr, nullptr, feat, N);

    // --- layer 3: 128 -> 32, 1 head, no activation; fused classifier head ---
    gemm_logits_kernel<128, 32, 4, 4, 1><<<cdiv(N, 128), 256>>>(
        feat, W3, a3s, a3d, lin, N, 128);
    gat_agg_kernel<1, 32, false, true><<<cdiv(N * 32, 256), 256>>>(
        lin, b3, Wc, bc, out, N);
}

// round 10
// speedup vs baseline: 1.4828x; 1.0303x over previous
#include <cuda_runtime.h>
#include <cuda_fp16.h>
#include <cstdint>

// Problem constants (fixed shapes)
#define NMAX 50000
#define EMAX 800000
#define FDIM 128      // H*C
#define HEADS4 4

// ---------------- scratch (device globals; no allocation allowed) ----------
__device__ float  g_lin [NMAX * FDIM];   // GEMM output (fp32, self-loop reads)
__device__ __half g_linh[NMAX * FDIM];   // fp16 copy for neighbor gathers
__device__ float  g_feat[NMAX * FDIM];   // activated features / layer IO
__device__ float  g_als [NMAX * HEADS4]; // per-node src logits
__device__ float  g_ald [NMAX * HEADS4]; // per-node dst logits
__device__ int    g_counts[NMAX];
__device__ int    g_indptr[NMAX + 1];
__device__ int    g_cursor[NMAX];
__device__ int    g_csr   [EMAX];        // src node per CSR-slot (grouped by dst)
__device__ int    g_scanbuf[NMAX];       // per-block exclusive scan
__device__ int    g_blocksum[64];        // per-scan1-block totals
__device__ int    g_is64;

static inline int cdiv(int a, int b) { return (a + b - 1) / b; }

// ------------- init: zero counts + dtype probe (int64 vs int32) ------------
// Values are in [0, 50000): if stored as int64, every odd 32-bit word is 0.
__global__ void init_kernel(const unsigned int* __restrict__ w, int n) {
    int i = blockIdx.x * blockDim.x + threadIdx.x;
    if (i < n) g_counts[i] = 0;
    if (blockIdx.x == 0) {
        __shared__ int any;
        if (threadIdx.x == 0) any = 0;
        __syncthreads();
        int acc = 0;
        for (int j = threadIdx.x; j < 2048; j += blockDim.x) acc |= (int)w[2 * j + 1];
        atomicOr(&any, acc);
        __syncthreads();
        if (threadIdx.x == 0) g_is64 = (any == 0) ? 1 : 0;
    }
}

__global__ void count_dst_kernel(const void* __restrict__ ei, int E) {
    int i = blockIdx.x * blockDim.x + threadIdx.x;
    if (i >= E) return;
    int d = g_is64 ? (int)((const long long*)ei)[(size_t)E + i]
                   : ((const int*)ei)[E + i];
    atomicAdd(&g_counts[d], 1);
}

// --- multi-block scan, stage 1: per-block (1024 elems) exclusive scan ------
__global__ void __launch_bounds__(1024) scan1_kernel(int n) {
    __shared__ int warpsum[32];
    int i = blockIdx.x * 1024 + threadIdx.x;
    int lane = threadIdx.x & 31, w = threadIdx.x >> 5;
    int v = (i < n) ? g_counts[i] : 0;
    int x = v;
#pragma unroll
    for (int d = 1; d < 32; d <<= 1) {
        int t = __shfl_up_sync(0xffffffffu, x, d);
        if (lane >= d) x += t;
    }
    if (lane == 31) warpsum[w] = x;
    __syncthreads();
    if (w == 0) {
        int s = warpsum[lane];
#pragma unroll
        for (int d = 1; d < 32; d <<= 1) {
            int t = __shfl_up_sync(0xffffffffu, s, d);
            if (lane >= d) s += t;
        }
        warpsum[lane] = s;
    }
    __syncthreads();
    int incl = x + (w > 0 ? warpsum[w - 1] : 0);
    if (i < n) g_scanbuf[i] = incl - v;                 // exclusive within block
    if (threadIdx.x == 1023) g_blocksum[blockIdx.x] = incl;
}

// --- stage 2+3 merged: every block redundantly scans the <=64 block sums ---
__global__ void scan23_kernel(int nb, int n) {
    __shared__ int sh[64];
    __shared__ int pre[64];
    int t = threadIdx.x;
    if (t < 64) sh[t] = (t < nb) ? g_blocksum[t] : 0;
    __syncthreads();
    for (int d = 1; d < 64; d <<= 1) {
        int x = 0;
        if (t < 64 && t >= d) x = sh[t - d];
        __syncthreads();
        if (t < 64) sh[t] += x;
        __syncthreads();
    }
    if (t < 64) {
        int v = (t < nb) ? g_blocksum[t] : 0;
        pre[t] = sh[t] - v;                             // exclusive block offset
    }
    __syncthreads();
    int i = blockIdx.x * blockDim.x + t;
    if (i < n) {
        int off = pre[i >> 10] + g_scanbuf[i];
        g_indptr[i] = off;
        g_cursor[i] = off;
    }
    if (blockIdx.x == 0 && t == 0) g_indptr[n] = sh[63];
}

__global__ void scatter_kernel(const void* __restrict__ ei, int E) {
    int i = blockIdx.x * blockDim.x + threadIdx.x;
    if (i >= E) return;
    int s, d;
    if (g_is64) {
        s = (int)((const long long*)ei)[i];
        d = (int)((const long long*)ei)[(size_t)E + i];
    } else {
        s = ((const int*)ei)[i];
        d = ((const int*)ei)[E + i];
    }
    int pos = atomicAdd(&g_cursor[d], 1);
    g_csr[pos] = s;
}

// ---------------- GEMM + fused attention logits ----------------------------
// C[M x BN] = A[M x K] @ B[K x BN]; BN == actual N == ldb. Single-buffered
// (proven inner loop). Epilogue stores fp32 C, an fp16 copy Ch for neighbor
// gathers, and the attention logits:
//   g_als[m][h] = <C[m, h*32:(h+1)*32], aS flattened>, g_ald likewise.
// Head h owns columns [h*32, h*32+32); per-thread partial dots on the
// register-resident acc reduce over the 8 lanes sharing rows+head via shfl.
template <int BM, int BN, int TM, int TN, int HEADS>
__global__ void __launch_bounds__(256) gemm_logits_kernel(
    const float* __restrict__ A, const float* __restrict__ B,
    const float* __restrict__ aS, const float* __restrict__ aD,
    float* __restrict__ C, __half* __restrict__ Ch, int M, int K)
{
    constexpr int BK = 16;
    constexpr int TX = BN / TN;
    constexpr int TY = BM / TM;
    static_assert(TX * TY == 256, "256 threads");
    static_assert(TM % 4 == 0 && TN % 4 == 0, "float4 fragments");
    static_assert(TX % 8 == 0, "8-lane logit reduce needs TX multiple of 8");
    constexpr int AG = TM / 4;             // float4 groups per thread in M
    constexpr int NG = TN / 4;             // float4 groups per thread in N
    constexpr int GS = BN / NG;            // group stride in columns
    constexpr int APAD = 4;

    __shared__ float As[BK][BM + APAD];
    __shared__ float Bs[BK][BN];

    int tid = threadIdx.x;
    int tx = tid % TX, ty = tid / TX;
    int m0 = blockIdx.x * BM;

    float acc[TM][TN];
#pragma unroll
    for (int i = 0; i < TM; i++)
#pragma unroll
        for (int j = 0; j < TN; j++) acc[i][j] = 0.f;

    for (int k0 = 0; k0 < K; k0 += BK) {
        constexpr int AE = BM * BK / 256;
#pragma unroll
        for (int i = 0; i < AE; i++) {
            int idx = tid + i * 256;
            int am = idx / BK, ak = idx % BK;
            int gm = m0 + am;
            As[ak][am] = (gm < M) ? A[(size_t)gm * K + k0 + ak] : 0.f;
        }
        constexpr int BE = BK * BN / 256;
#pragma unroll
        for (int i = 0; i < BE; i++) {
            int idx = tid + i * 256;
            int bk = idx / BN, bn = idx % BN;
            Bs[bk][bn] = B[(size_t)(k0 + bk) * BN + bn];
        }
        __syncthreads();
#pragma unroll
        for (int k = 0; k < BK; k++) {
            float a[TM];
#pragma unroll
            for (int g = 0; g < AG; g++) {
                float4 av = *(const float4*)&As[k][ty * TM + g * 4];
                a[g * 4 + 0] = av.x; a[g * 4 + 1] = av.y;
                a[g * 4 + 2] = av.z; a[g * 4 + 3] = av.w;
            }
            float b[TN];
#pragma unroll
            for (int g = 0; g < NG; g++) {
                float4 bv = *(const float4*)&Bs[k][g * GS + tx * 4];
                b[g * 4 + 0] = bv.x; b[g * 4 + 1] = bv.y;
                b[g * 4 + 2] = bv.z; b[g * 4 + 3] = bv.w;
            }
#pragma unroll
            for (int i = 0; i < TM; i++)
#pragma unroll
                for (int j = 0; j < TN; j++) acc[i][j] += a[i] * b[j];
        }
        __syncthreads();
    }

    // epilogue: C store (fp32 + fp16 copy) + fused logits
#pragma unroll
    for (int i = 0; i < TM; i++) {
        int gm = m0 + ty * TM + i;
#pragma unroll
        for (int g = 0; g < NG; g++) {
            int colbase = g * GS + tx * 4;
            float4 v = make_float4(acc[i][g * 4 + 0], acc[i][g * 4 + 1],
                                   acc[i][g * 4 + 2], acc[i][g * 4 + 3]);
            if (gm < M) {
                *(float4*)&C[(size_t)gm * BN + colbase] = v;
                __half2 h01 = __floats2half2_rn(v.x, v.y);
                __half2 h23 = __floats2half2_rn(v.z, v.w);
                uint2 hp;
                hp.x = *(unsigned int*)&h01;
                hp.y = *(unsigned int*)&h23;
                *(uint2*)&Ch[(size_t)gm * BN + colbase] = hp;
            }
            float pS = v.x * aS[colbase]     + v.y * aS[colbase + 1]
                     + v.z * aS[colbase + 2] + v.w * aS[colbase + 3];
            float pD = v.x * aD[colbase]     + v.y * aD[colbase + 1]
                     + v.z * aD[colbase + 2] + v.w * aD[colbase + 3];
#pragma unroll
            for (int off = 4; off; off >>= 1) {
                pS += __shfl_xor_sync(0xffffffffu, pS, off);
                pD += __shfl_xor_sync(0xffffffffu, pD, off);
            }
            if ((tx & 7) == 0 && gm < M) {
                int head = colbase >> 5;        // CH = 32 columns per head
                g_als[gm * HEADS + head] = pS;
                g_ald[gm * HEADS + head] = pD;
            }
        }
    }
}

// ---------------- GAT aggregation: one warp per destination node -----------
// Pass A max, pass B denom, pass C aggregate (fp16 neighbor gathers, fp32
// self-loop + accumulation). Self-loop handled analytically. Optional fused
// classifier head for layer 3.
template <int HEADS, int CH, bool ACT, bool FUSE_HEAD>
__global__ void __launch_bounds__(256) gat_agg_kernel(
    const float* __restrict__ h, const __half* __restrict__ hh,
    const float* __restrict__ bias,
    const float* __restrict__ Wc, const float* __restrict__ bc,
    float* __restrict__ out, int n)
{
    constexpr int F = HEADS * CH;
    constexpr int CL = F / 32;                 // channels per lane
    int warp = (blockIdx.x * blockDim.x + threadIdx.x) >> 5;
    int lane = threadIdx.x & 31;
    if (warp >= n) return;

    int start = g_indptr[warp], end = g_indptr[warp + 1];

    float aldv[HEADS], self_e[HEADS], m[HEADS];
    if constexpr (HEADS == 4) {
        float4 t = *(const float4*)&g_ald[warp * 4];
        aldv[0] = t.x; aldv[1] = t.y; aldv[2] = t.z; aldv[3] = t.w;
        float4 u = *(const float4*)&g_als[warp * 4];
        float sv[4] = {u.x, u.y, u.z, u.w};
#pragma unroll
        for (int hh2 = 0; hh2 < 4; hh2++) {
            float e = sv[hh2] + aldv[hh2];
            e = e > 0.f ? e : 0.2f * e;
            self_e[hh2] = e; m[hh2] = e;
        }
    } else {
        aldv[0] = g_ald[warp];
        float e = g_als[warp] + aldv[0];
        e = e > 0.f ? e : 0.2f * e;
        self_e[0] = e; m[0] = e;
    }

    // pass A: max
    for (int eb = start; eb < end; eb += 32) {
        int e = eb + lane;
        if (e < end) {
            int s = g_csr[e];
            if constexpr (HEADS == 4) {
                float4 u = *(const float4*)&g_als[s * 4];
                float sv[4] = {u.x, u.y, u.z, u.w};
#pragma unroll
                for (int hh2 = 0; hh2 < 4; hh2++) {
                    float x = sv[hh2] + aldv[hh2];
                    x = x > 0.f ? x : 0.2f * x;
                    m[hh2] = fmaxf(m[hh2], x);
                }
            } else {
                float x = g_als[s] + aldv[0];
                x = x > 0.f ? x : 0.2f * x;
                m[0] = fmaxf(m[0], x);
            }
        }
    }
#pragma unroll
    for (int hh2 = 0; hh2 < HEADS; hh2++)
#pragma unroll
        for (int off = 16; off; off >>= 1)
            m[hh2] = fmaxf(m[hh2], __shfl_xor_sync(0xffffffffu, m[hh2], off));

    // pass B: denom
    float den[HEADS];
#pragma unroll
    for (int hh2 = 0; hh2 < HEADS; hh2++) den[hh2] = 0.f;
    for (int eb = start; eb < end; eb += 32) {
        int e = eb + lane;
        if (e < end) {
            int s = g_csr[e];
            if constexpr (HEADS == 4) {
                float4 u = *(const float4*)&g_als[s * 4];
                float sv[4] = {u.x, u.y, u.z, u.w};
#pragma unroll
                for (int hh2 = 0; hh2 < 4; hh2++) {
                    float x = sv[hh2] + aldv[hh2];
                    x = x > 0.f ? x : 0.2f * x;
                    den[hh2] += __expf(x - m[hh2]);
                }
            } else {
                float x = g_als[s] + aldv[0];
                x = x > 0.f ? x : 0.2f * x;
                den[0] += __expf(x - m[0]);
            }
        }
    }
#pragma unroll
    for (int hh2 = 0; hh2 < HEADS; hh2++) {
#pragma unroll
        for (int off = 16; off; off >>= 1)
            den[hh2] += __shfl_xor_sync(0xffffffffu, den[hh2], off);
        den[hh2] += __expf(self_e[hh2] - m[hh2]);
        den[hh2] = 1.f / (den[hh2] + 1e-16f);
    }

    // pass C: aggregate. Lane owns channels [lane*CL, lane*CL+CL), one head.
    int myhead = (HEADS == 1) ? 0 : (lane >> 3);
    float mym = m[myhead], myden = den[myhead], mya = aldv[myhead];
    float acc[CL];
    {
        // self-loop message from the fp32 copy (largest alpha, keep exact)
        float alpha = __expf(self_e[myhead] - mym) * myden;
        if constexpr (CL == 4) {
            float4 hv = *(const float4*)&h[(size_t)warp * F + lane * 4];
            acc[0] = hv.x * alpha; acc[1] = hv.y * alpha;
            acc[2] = hv.z * alpha; acc[3] = hv.w * alpha;
        } else {
            acc[0] = h[(size_t)warp * F + lane] * alpha;
        }
    }
    int s = (start < end) ? g_csr[start] : 0;   // prefetch pipeline
    for (int e = start; e < end; e++) {
        int snext = (e + 1 < end) ? g_csr[e + 1] : 0;
        float x = g_als[s * HEADS + myhead] + mya;
        x = x > 0.f ? x : 0.2f * x;
        float alpha = __expf(x - mym) * myden;
        if constexpr (CL == 4) {
            uint2 raw = *(const uint2*)&hh[(size_t)s * F + lane * 4];
            float2 f01 = __half22float2(*(__half2*)&raw.x);
            float2 f23 = __half22float2(*(__half2*)&raw.y);
            acc[0] += f01.x * alpha; acc[1] += f01.y * alpha;
            acc[2] += f23.x * alpha; acc[3] += f23.y * alpha;
        } else {
            acc[0] += __half2float(hh[(size_t)s * F + lane]) * alpha;
        }
        s = snext;
    }

    if constexpr (FUSE_HEAD) {
        // layer 3: write link embedding + classifier logits directly to out
        float v = acc[0] + bias[lane];
        out[(size_t)n * 2 + (size_t)warp * 32 + lane] = v;
        float p0 = v * Wc[lane * 2 + 0];
        float p1 = v * Wc[lane * 2 + 1];
#pragma unroll
        for (int off = 16; off; off >>= 1) {
            p0 += __shfl_xor_sync(0xffffffffu, p0, off);
            p1 += __shfl_xor_sync(0xffffffffu, p1, off);
        }
        if (lane == 0) {
            out[(size_t)warp * 2 + 0] = p0 + bc[0];
            out[(size_t)warp * 2 + 1] = p1 + bc[1];
        }
    } else {
#pragma unroll
        for (int j = 0; j < CL; j++) {
            int c = lane * CL + j;
            float v = acc[j] + bias[c];
            if (ACT) v = v > 0.f ? v : (__expf(v) - 1.f);
            out[(size_t)warp * F + c] = v;
        }
    }
}

// ---------------- launch ----------------------------------------------------
extern "C" void kernel_launch(void* const* d_in, const int* in_sizes, int n_in,
                              void* d_out, int out_size)
{
    const float*  x    = (const float*)d_in[0];
    const void*   ei   = d_in[1];
    const float*  W1   = (const float*)d_in[2];
    const float*  a1s  = (const float*)d_in[3];
    const float*  a1d  = (const float*)d_in[4];
    const float*  b1   = (const float*)d_in[5];
    const float*  W2   = (const float*)d_in[6];
    const float*  a2s  = (const float*)d_in[7];
    const float*  a2d  = (const float*)d_in[8];
    const float*  b2   = (const float*)d_in[9];
    const float*  W3   = (const float*)d_in[10];
    const float*  a3s  = (const float*)d_in[11];
    const float*  a3d  = (const float*)d_in[12];
    const float*  b3   = (const float*)d_in[13];
    const float*  Wc   = (const float*)d_in[14];
    const float*  bc   = (const float*)d_in[15];
    float* out = (float*)d_out;

    int N = in_sizes[0] / FDIM;     // 50000
    int E = in_sizes[1] / 2;        // 800000 (element count same for i32/i64)

    float  *lin, *feat;
    __half *linh;
    cudaGetSymbolAddress((void**)&lin,  g_lin);
    cudaGetSymbolAddress((void**)&linh, g_linh);
    cudaGetSymbolAddress((void**)&feat, g_feat);

    // --- CSR by destination (rebuilt every replay; deterministic work) ---
    init_kernel<<<cdiv(N, 256), 256>>>((const unsigned int*)ei, N);
    count_dst_kernel<<<cdiv(E, 256), 256>>>(ei, E);
    int nb = cdiv(N, 1024);
    scan1_kernel<<<nb, 1024>>>(N);
    scan23_kernel<<<cdiv(N, 256), 256>>>(nb, N);
    scatter_kernel<<<cdiv(E, 256), 256>>>(ei, E);

    // --- layer 1: x[128] -> 128, 4 heads, ELU ---
    gemm_logits_kernel<128, 128, 8, 8, 4><<<cdiv(N, 128), 256>>>(
        x, W1, a1s, a1d, lin, linh, N, 128);
    gat_agg_kernel<4, 32, true, false><<<cdiv(N * 32, 256), 256>>>(
        lin, linh, b1, nullptr, nullptr, feat, N);

    // --- layer 2: 128 -> 128, 4 heads, ELU ---
    gemm_logits_kernel<128, 128, 8, 8, 4><<<cdiv(N, 128), 256>>>(
        feat, W2, a2s, a2d, lin, linh, N, 128);
    gat_agg_kernel<4, 32, true, false><<<cdiv(N * 32, 256), 256>>>(
        lin, linh, b2, nullptr, nullptr, feat, N);

    // --- layer 3: 128 -> 32, 1 head, no activation; fused classifier head ---
    gemm_logits_kernel<128, 32, 4, 4, 1><<<cdiv(N, 128), 256>>>(
        feat, W3, a3s, a3d, lin, linh, N, 128);
    gat_agg_kernel<1, 32, false, true><<<cdiv(N * 32, 256), 256>>>(
        lin, linh, b3, Wc, bc, out, N);
}

// round 12
// speedup vs baseline: 1.7272x; 1.1649x over previous
#include <cuda_runtime.h>
#include <cuda_fp16.h>
#include <cstdint>

// Problem constants (fixed shapes)
#define NMAX 50000
#define EMAX 800000
#define FDIM 128      // H*C
#define HEADS4 4

// ---------------- scratch (device globals; no allocation allowed) ----------
__device__ float  g_lin [NMAX * FDIM];   // GEMM output (fp32, self-loop reads)
__device__ __half g_linh[NMAX * FDIM];   // fp16 copy for neighbor gathers
__device__ float  g_feat[NMAX * FDIM];   // activated features / layer IO
__device__ float  g_als [NMAX * HEADS4]; // per-node src logits
__device__ float  g_ald [NMAX * HEADS4]; // per-node dst logits
__device__ int    g_counts[NMAX];
__device__ int    g_indptr[NMAX + 1];
__device__ int    g_cursor[NMAX];
__device__ int    g_csr   [EMAX];        // src node per CSR-slot (grouped by dst)
__device__ int    g_scanbuf[NMAX];       // per-block exclusive scan
__device__ int    g_blocksum[64];        // per-scan1-block totals
__device__ int    g_is64;

static inline int cdiv(int a, int b) { return (a + b - 1) / b; }

// ---------------- cp.async helpers ----------------------------------------
__device__ __forceinline__ unsigned smem_u32p(const void* p) {
    return (unsigned)__cvta_generic_to_shared(p);
}
#define CP4(dst, src)  asm volatile("cp.async.ca.shared.global [%0], [%1], 4;"  :: "r"(dst), "l"(src))
#define CP16(dst, src) asm volatile("cp.async.cg.shared.global [%0], [%1], 16;" :: "r"(dst), "l"(src))
#define CPCOMMIT()     asm volatile("cp.async.commit_group;")
#define CPWAIT0()      asm volatile("cp.async.wait_group 0;" ::: "memory")

// ------------- init: zero counts + dtype probe (int64 vs int32) ------------
// Values are in [0, 50000): if stored as int64, every odd 32-bit word is 0.
__global__ void init_kernel(const unsigned int* __restrict__ w, int n) {
    int i = blockIdx.x * blockDim.x + threadIdx.x;
    if (i < n) g_counts[i] = 0;
    if (blockIdx.x == 0) {
        __shared__ int any;
        if (threadIdx.x == 0) any = 0;
        __syncthreads();
        int acc = 0;
        for (int j = threadIdx.x; j < 2048; j += blockDim.x) acc |= (int)w[2 * j + 1];
        atomicOr(&any, acc);
        __syncthreads();
        if (threadIdx.x == 0) g_is64 = (any == 0) ? 1 : 0;
    }
}

__global__ void count_dst_kernel(const void* __restrict__ ei, int E) {
    int i = blockIdx.x * blockDim.x + threadIdx.x;
    if (i >= E) return;
    int d = g_is64 ? (int)((const long long*)ei)[(size_t)E + i]
                   : ((const int*)ei)[E + i];
    atomicAdd(&g_counts[d], 1);
}

// --- multi-block scan, stage 1: per-block (1024 elems) exclusive scan ------
__global__ void __launch_bounds__(1024) scan1_kernel(int n) {
    __shared__ int warpsum[32];
    int i = blockIdx.x * 1024 + threadIdx.x;
    int lane = threadIdx.x & 31, w = threadIdx.x >> 5;
    int v = (i < n) ? g_counts[i] : 0;
    int x = v;
#pragma unroll
    for (int d = 1; d < 32; d <<= 1) {
        int t = __shfl_up_sync(0xffffffffu, x, d);
        if (lane >= d) x += t;
    }
    if (lane == 31) warpsum[w] = x;
    __syncthreads();
    if (w == 0) {
        int s = warpsum[lane];
#pragma unroll
        for (int d = 1; d < 32; d <<= 1) {
            int t = __shfl_up_sync(0xffffffffu, s, d);
            if (lane >= d) s += t;
        }
        warpsum[lane] = s;
    }
    __syncthreads();
    int incl = x + (w > 0 ? warpsum[w - 1] : 0);
    if (i < n) g_scanbuf[i] = incl - v;                 // exclusive within block
    if (threadIdx.x == 1023) g_blocksum[blockIdx.x] = incl;
}

// --- stage 2+3 merged: every block redundantly scans the <=64 block sums ---
__global__ void scan23_kernel(int nb, int n) {
    __shared__ int sh[64];
    __shared__ int pre[64];
    int t = threadIdx.x;
    if (t < 64) sh[t] = (t < nb) ? g_blocksum[t] : 0;
    __syncthreads();
    for (int d = 1; d < 64; d <<= 1) {
        int x = 0;
        if (t < 64 && t >= d) x = sh[t - d];
        __syncthreads();
        if (t < 64) sh[t] += x;
        __syncthreads();
    }
    if (t < 64) {
        int v = (t < nb) ? g_blocksum[t] : 0;
        pre[t] = sh[t] - v;                             // exclusive block offset
    }
    __syncthreads();
    int i = blockIdx.x * blockDim.x + t;
    if (i < n) {
        int off = pre[i >> 10] + g_scanbuf[i];
        g_indptr[i] = off;
        g_cursor[i] = off;
    }
    if (blockIdx.x == 0 && t == 0) g_indptr[n] = sh[63];
}

__global__ void scatter_kernel(const void* __restrict__ ei, int E) {
    int i = blockIdx.x * blockDim.x + threadIdx.x;
    if (i >= E) return;
    int s, d;
    if (g_is64) {
        s = (int)((const long long*)ei)[i];
        d = (int)((const long long*)ei)[(size_t)E + i];
    } else {
        s = ((const int*)ei)[i];
        d = ((const int*)ei)[E + i];
    }
    int pos = atomicAdd(&g_cursor[d], 1);
    g_csr[pos] = s;
}

// ---------------- GEMM + fused attention logits ----------------------------
// C[M x BN] = A[M x K] @ B[K x BN]; BN == actual N == ldb. 2-stage cp.async
// pipeline (no register staging -> no spill pressure), 1 sync/tile; load of
// tile t+1 overlaps compute of tile t. A rows clamped at M-1 (those accs are
// never stored). Epilogue stores fp32 C, fp16 copy Ch, and attention logits:
//   g_als[m][h] = <C[m, h*32:(h+1)*32], aS flattened>, g_ald likewise.
template <int BM, int BN, int TM, int TN, int HEADS>
__global__ void __launch_bounds__(256) gemm_logits_kernel(
    const float* __restrict__ A, const float* __restrict__ B,
    const float* __restrict__ aS, const float* __restrict__ aD,
    float* __restrict__ C, __half* __restrict__ Ch, int M, int K)
{
    constexpr int BK = 16;
    constexpr int TX = BN / TN;
    constexpr int TY = BM / TM;
    static_assert(TX * TY == 256, "256 threads");
    static_assert(TM % 4 == 0 && TN % 4 == 0, "float4 fragments");
    static_assert(TX % 8 == 0, "8-lane logit reduce needs TX multiple of 8");
    constexpr int AG = TM / 4;             // float4 groups per thread in M
    constexpr int NG = TN / 4;             // float4 groups per thread in N
    constexpr int GS = BN / NG;            // group stride in columns
    constexpr int APAD = 4;
    constexpr int AE  = BM * BK / 256;     // A elems per thread per tile
    constexpr int BF4 = BK * BN / 4;       // float4 count in B tile
    constexpr int BI  = (BF4 + 255) / 256;

    __shared__ float As[2][BK][BM + APAD];
    __shared__ float Bs[2][BK][BN];

    int tid = threadIdx.x;
    int tx = tid % TX, ty = tid / TX;
    int m0 = blockIdx.x * BM;

    auto issue = [&](int t) {
        int st = t & 1;
        int k0 = t * BK;
#pragma unroll
        for (int i = 0; i < AE; i++) {
            int idx = tid + i * 256;
            int am = idx / BK, ak = idx % BK;
            int gm = m0 + am;
            if (gm > M - 1) gm = M - 1;     // clamp: garbage rows never stored
            CP4(smem_u32p(&As[st][ak][am]), &A[(size_t)gm * K + k0 + ak]);
        }
#pragma unroll
        for (int i = 0; i < BI; i++) {
            int f = tid + i * 256;
            if (f < BF4) {
                int bk = f / (BN / 4), bn = (f % (BN / 4)) * 4;
                CP16(smem_u32p(&Bs[st][bk][bn]), &B[(size_t)(k0 + bk) * BN + bn]);
            }
        }
        CPCOMMIT();
    };

    float acc[TM][TN];
#pragma unroll
    for (int i = 0; i < TM; i++)
#pragma unroll
        for (int j = 0; j < TN; j++) acc[i][j] = 0.f;

    issue(0);
    int T = K / BK;
    for (int t = 0; t < T; t++) {
        CPWAIT0();
        __syncthreads();
        if (t + 1 < T) issue(t + 1);
        int p = t & 1;
#pragma unroll
        for (int k = 0; k < BK; k++) {
            float a[TM];
#pragma unroll
            for (int g = 0; g < AG; g++) {
                float4 av = *(const float4*)&As[p][k][ty * TM + g * 4];
                a[g * 4 + 0] = av.x; a[g * 4 + 1] = av.y;
                a[g * 4 + 2] = av.z; a[g * 4 + 3] = av.w;
            }
            float b[TN];
#pragma unroll
            for (int g = 0; g < NG; g++) {
                float4 bv = *(const float4*)&Bs[p][k][g * GS + tx * 4];
                b[g * 4 + 0] = bv.x; b[g * 4 + 1] = bv.y;
                b[g * 4 + 2] = bv.z; b[g * 4 + 3] = bv.w;
            }
#pragma unroll
            for (int i = 0; i < TM; i++)
#pragma unroll
                for (int j = 0; j < TN; j++) acc[i][j] += a[i] * b[j];
        }
    }

    // epilogue: C store (fp32 + fp16 copy) + fused logits
#pragma unroll
    for (int i = 0; i < TM; i++) {
        int gm = m0 + ty * TM + i;
#pragma unroll
        for (int g = 0; g < NG; g++) {
            int colbase = g * GS + tx * 4;
            float4 v = make_float4(acc[i][g * 4 + 0], acc[i][g * 4 + 1],
                                   acc[i][g * 4 + 2], acc[i][g * 4 + 3]);
            if (gm < M) {
                *(float4*)&C[(size_t)gm * BN + colbase] = v;
                __half2 h01 = __floats2half2_rn(v.x, v.y);
                __half2 h23 = __floats2half2_rn(v.z, v.w);
                uint2 hp;
                hp.x = *(unsigned int*)&h01;
                hp.y = *(unsigned int*)&h23;
                *(uint2*)&Ch[(size_t)gm * BN + colbase] = hp;
            }
            float pS = v.x * aS[colbase]     + v.y * aS[colbase + 1]
                     + v.z * aS[colbase + 2] + v.w * aS[colbase + 3];
            float pD = v.x * aD[colbase]     + v.y * aD[colbase + 1]
                     + v.z * aD[colbase + 2] + v.w * aD[colbase + 3];
#pragma unroll
            for (int off = 4; off; off >>= 1) {
                pS += __shfl_xor_sync(0xffffffffu, pS, off);
                pD += __shfl_xor_sync(0xffffffffu, pD, off);
            }
            if ((tx & 7) == 0 && gm < M) {
                int head = colbase >> 5;        // CH = 32 columns per head
                g_als[gm * HEADS + head] = pS;
                g_ald[gm * HEADS + head] = pD;
            }
        }
    }
}

// ---------------- GAT aggregation: one warp per destination node -----------
// Pass A max, pass B denom (unchanged). Pass C: per 32-edge chunk, lanes
// compute all heads' alphas in parallel into smem (1 gather + HEADS exps per
// edge total), then the serial channel loop reads alpha/src from smem and only
// does the fp16 h-gather, 2-way unrolled. Self-loop analytic (fp32).
template <int HEADS, int CH, bool ACT, bool FUSE_HEAD>
__global__ void __launch_bounds__(256) gat_agg_kernel(
    const float* __restrict__ h, const __half* __restrict__ hh,
    const float* __restrict__ bias,
    const float* __restrict__ Wc, const float* __restrict__ bc,
    float* __restrict__ out, int n)
{
    constexpr int F = HEADS * CH;
    constexpr int CL = F / 32;                 // channels per lane
    __shared__ float s_alpha[8][32 * HEADS];
    __shared__ int   s_src[8][32];
    int wslot = threadIdx.x >> 5;
    int warp = (blockIdx.x * blockDim.x + threadIdx.x) >> 5;
    int lane = threadIdx.x & 31;
    if (warp >= n) return;

    int start = g_indptr[warp], end = g_indptr[warp + 1];

    float aldv[HEADS], self_e[HEADS], m[HEADS];
    if constexpr (HEADS == 4) {
        float4 t = *(const float4*)&g_ald[warp * 4];
        aldv[0] = t.x; aldv[1] = t.y; aldv[2] = t.z; aldv[3] = t.w;
        float4 u = *(const float4*)&g_als[warp * 4];
        float sv[4] = {u.x, u.y, u.z, u.w};
#pragma unroll
        for (int hx = 0; hx < 4; hx++) {
            float e = sv[hx] + aldv[hx];
            e = e > 0.f ? e : 0.2f * e;
            self_e[hx] = e; m[hx] = e;
        }
    } else {
        aldv[0] = g_ald[warp];
        float e = g_als[warp] + aldv[0];
        e = e > 0.f ? e : 0.2f * e;
        self_e[0] = e; m[0] = e;
    }

    // pass A: max
    for (int eb = start; eb < end; eb += 32) {
        int e = eb + lane;
        if (e < end) {
            int s = g_csr[e];
            if constexpr (HEADS == 4) {
                float4 u = *(const float4*)&g_als[s * 4];
                float sv[4] = {u.x, u.y, u.z, u.w};
#pragma unroll
                for (int hx = 0; hx < 4; hx++) {
                    float x = sv[hx] + aldv[hx];
                    x = x > 0.f ? x : 0.2f * x;
                    m[hx] = fmaxf(m[hx], x);
                }
            } else {
                float x = g_als[s] + aldv[0];
                x = x > 0.f ? x : 0.2f * x;
                m[0] = fmaxf(m[0], x);
            }
        }
    }
#pragma unroll
    for (int hx = 0; hx < HEADS; hx++)
#pragma unroll
        for (int off = 16; off; off >>= 1)
            m[hx] = fmaxf(m[hx], __shfl_xor_sync(0xffffffffu, m[hx], off));

    // pass B: denom
    float den[HEADS];
#pragma unroll
    for (int hx = 0; hx < HEADS; hx++) den[hx] = 0.f;
    for (int eb = start; eb < end; eb += 32) {
        int e = eb + lane;
        if (e < end) {
            int s = g_csr[e];
            if constexpr (HEADS == 4) {
                float4 u = *(const float4*)&g_als[s * 4];
                float sv[4] = {u.x, u.y, u.z, u.w};
#pragma unroll
                for (int hx = 0; hx < 4; hx++) {
                    float x = sv[hx] + aldv[hx];
                    x = x > 0.f ? x : 0.2f * x;
                    den[hx] += __expf(x - m[hx]);
                }
            } else {
                float x = g_als[s] + aldv[0];
                x = x > 0.f ? x : 0.2f * x;
                den[0] += __expf(x - m[0]);
            }
        }
    }
#pragma unroll
    for (int hx = 0; hx < HEADS; hx++) {
#pragma unroll
        for (int off = 16; off; off >>= 1)
            den[hx] += __shfl_xor_sync(0xffffffffu, den[hx], off);
        den[hx] += __expf(self_e[hx] - m[hx]);
        den[hx] = 1.f / (den[hx] + 1e-16f);
    }

    // pass C: chunked. Lane owns channels [lane*CL, lane*CL+CL), one head.
    int myhead = (HEADS == 1) ? 0 : (lane >> 3);
    float acc[CL];
    {
        // self-loop message from the fp32 copy (largest alpha, keep exact)
        float alpha = __expf(self_e[myhead] - m[myhead]) * den[myhead];
        if constexpr (CL == 4) {
            float4 hv = *(const float4*)&h[(size_t)warp * F + lane * 4];
            acc[0] = hv.x * alpha; acc[1] = hv.y * alpha;
            acc[2] = hv.z * alpha; acc[3] = hv.w * alpha;
        } else {
            acc[0] = h[(size_t)warp * F + lane] * alpha;
        }
    }
    for (int cs = start; cs < end; cs += 32) {
        int cnt = min(32, end - cs);
        // parallel phase: alphas for up to 32 edges, all heads
        if (lane < cnt) {
            int s = g_csr[cs + lane];
            s_src[wslot][lane] = s;
            if constexpr (HEADS == 4) {
                float4 u = *(const float4*)&g_als[s * 4];
                float sv[4] = {u.x, u.y, u.z, u.w};
                float al[4];
#pragma unroll
                for (int hx = 0; hx < 4; hx++) {
                    float x = sv[hx] + aldv[hx];
                    x = x > 0.f ? x : 0.2f * x;
                    al[hx] = __expf(x - m[hx]) * den[hx];
                }
                *(float4*)&s_alpha[wslot][lane * 4] =
                    make_float4(al[0], al[1], al[2], al[3]);
            } else {
                float x = g_als[s] + aldv[0];
                x = x > 0.f ? x : 0.2f * x;
                s_alpha[wslot][lane] = __expf(x - m[0]) * den[0];
            }
        }
        __syncwarp();
        // serial phase: only the fp16 h-gather, 2-way unrolled
        int j = 0;
        for (; j + 1 < cnt; j += 2) {
            int s0 = s_src[wslot][j], s1 = s_src[wslot][j + 1];
            float a0, a1;
            if constexpr (HEADS == 4) {
                a0 = s_alpha[wslot][j * 4 + myhead];
                a1 = s_alpha[wslot][j * 4 + 4 + myhead];
            } else {
                a0 = s_alpha[wslot][j];
                a1 = s_alpha[wslot][j + 1];
            }
            if constexpr (CL == 4) {
                uint2 r0 = *(const uint2*)&hh[(size_t)s0 * F + lane * 4];
                uint2 r1 = *(const uint2*)&hh[(size_t)s1 * F + lane * 4];
                float2 f0a = __half22float2(*(__half2*)&r0.x);
                float2 f0b = __half22float2(*(__half2*)&r0.y);
                float2 f1a = __half22float2(*(__half2*)&r1.x);
                float2 f1b = __half22float2(*(__half2*)&r1.y);
                acc[0] += f0a.x * a0 + f1a.x * a1;
                acc[1] += f0a.y * a0 + f1a.y * a1;
                acc[2] += f0b.x * a0 + f1b.x * a1;
                acc[3] += f0b.y * a0 + f1b.y * a1;
            } else {
                acc[0] += __half2float(hh[(size_t)s0 * F + lane]) * a0
                        + __half2float(hh[(size_t)s1 * F + lane]) * a1;
            }
        }
        if (j < cnt) {
            int s0 = s_src[wslot][j];
            float a0 = (HEADS == 4) ? s_alpha[wslot][j * 4 + myhead]
                                    : s_alpha[wslot][j];
            if constexpr (CL == 4) {
                uint2 r0 = *(const uint2*)&hh[(size_t)s0 * F + lane * 4];
                float2 f0a = __half22float2(*(__half2*)&r0.x);
                float2 f0b = __half22float2(*(__half2*)&r0.y);
                acc[0] += f0a.x * a0; acc[1] += f0a.y * a0;
                acc[2] += f0b.x * a0; acc[3] += f0b.y * a0;
            } else {
                acc[0] += __half2float(hh[(size_t)s0 * F + lane]) * a0;
            }
        }
        __syncwarp();
    }

    if constexpr (FUSE_HEAD) {
        // layer 3: write link embedding + classifier logits directly to out
        float v = acc[0] + bias[lane];
        out[(size_t)n * 2 + (size_t)warp * 32 + lane] = v;
        float p0 = v * Wc[lane * 2 + 0];
        float p1 = v * Wc[lane * 2 + 1];
#pragma unroll
        for (int off = 16; off; off >>= 1) {
            p0 += __shfl_xor_sync(0xffffffffu, p0, off);
            p1 += __shfl_xor_sync(0xffffffffu, p1, off);
        }
        if (lane == 0) {
            out[(size_t)warp * 2 + 0] = p0 + bc[0];
            out[(size_t)warp * 2 + 1] = p1 + bc[1];
        }
    } else {
#pragma unroll
        for (int j = 0; j < CL; j++) {
            int c = lane * CL + j;
            float v = acc[j] + bias[c];
            if (ACT) v = v > 0.f ? v : (__expf(v) - 1.f);
            out[(size_t)warp * F + c] = v;
        }
    }
}

// ---------------- launch ----------------------------------------------------
extern "C" void kernel_launch(void* const* d_in, const int* in_sizes, int n_in,
                              void* d_out, int out_size)
{
    const float*  x    = (const float*)d_in[0];
    const void*   ei   = d_in[1];
    const float*  W1   = (const float*)d_in[2];
    const float*  a1s  = (const float*)d_in[3];
    const float*  a1d  = (const float*)d_in[4];
    const float*  b1   = (const float*)d_in[5];
    const float*  W2   = (const float*)d_in[6];
    const float*  a2s  = (const float*)d_in[7];
    const float*  a2d  = (const float*)d_in[8];
    const float*  b2   = (const float*)d_in[9];
    const float*  W3   = (const float*)d_in[10];
    const float*  a3s  = (const float*)d_in[11];
    const float*  a3d  = (const float*)d_in[12];
    const float*  b3   = (const float*)d_in[13];
    const float*  Wc   = (const float*)d_in[14];
    const float*  bc   = (const float*)d_in[15];
    float* out = (float*)d_out;

    int N = in_sizes[0] / FDIM;     // 50000
    int E = in_sizes[1] / 2;        // 800000 (element count same for i32/i64)

    float  *lin, *feat;
    __half *linh;
    cudaGetSymbolAddress((void**)&lin,  g_lin);
    cudaGetSymbolAddress((void**)&linh, g_linh);
    cudaGetSymbolAddress((void**)&feat, g_feat);

    // --- CSR by destination (rebuilt every replay; deterministic work) ---
    init_kernel<<<cdiv(N, 256), 256>>>((const unsigned int*)ei, N);
    count_dst_kernel<<<cdiv(E, 256), 256>>>(ei, E);
    int nb = cdiv(N, 1024);
    scan1_kernel<<<nb, 1024>>>(N);
    scan23_kernel<<<cdiv(N, 256), 256>>>(nb, N);
    scatter_kernel<<<cdiv(E, 256), 256>>>(ei, E);

    // --- layer 1: x[128] -> 128, 4 heads, ELU ---
    gemm_logits_kernel<128, 128, 8, 8, 4><<<cdiv(N, 128), 256>>>(
        x, W1, a1s, a1d, lin, linh, N, 128);
    gat_agg_kernel<4, 32, true, false><<<cdiv(N * 32, 256), 256>>>(
        lin, linh, b1, nullptr, nullptr, feat, N);

    // --- layer 2: 128 -> 128, 4 heads, ELU ---
    gemm_logits_kernel<128, 128, 8, 8, 4><<<cdiv(N, 128), 256>>>(
        feat, W2, a2s, a2d, lin, linh, N, 128);
    gat_agg_kernel<4, 32, true, false><<<cdiv(N * 32, 256), 256>>>(
        lin, linh, b2, nullptr, nullptr, feat, N);

    // --- layer 3: 128 -> 32, 1 head, no activation; fused classifier head ---
    gemm_logits_kernel<128, 32, 4, 4, 1><<<cdiv(N, 128), 256>>>(
        feat, W3, a3s, a3d, lin, linh, N, 128);
    gat_agg_kernel<1, 32, false, true><<<cdiv(N * 32, 256), 256>>>(
        lin, linh, b3, Wc, bc, out, N);
}

// round 13
// speedup vs baseline: 1.8438x; 1.0675x over previous
#include <cuda_runtime.h>
#include <cuda_fp16.h>
#include <cstdint>

// Problem constants (fixed shapes)
#define NMAX 50000
#define EMAX 800000
#define FDIM 128      // H*C
#define HEADS4 4

// ---------------- scratch (device globals; no allocation allowed) ----------
__device__ float  g_lin [NMAX * FDIM];   // GEMM output (fp32, self-loop reads)
__device__ __half g_linh[NMAX * FDIM];   // fp16 copy for neighbor gathers
__device__ float  g_feat[NMAX * FDIM];   // activated features / layer IO
__device__ float  g_als [NMAX * HEADS4]; // per-node src logits
__device__ float  g_ald [NMAX * HEADS4]; // per-node dst logits
__device__ int    g_counts[NMAX];
__device__ int    g_indptr[NMAX + 1];
__device__ int    g_cursor[NMAX];
__device__ int    g_csr   [EMAX];        // src node per CSR-slot (grouped by dst)
__device__ int    g_scanbuf[NMAX];       // per-block exclusive scan
__device__ int    g_blocksum[64];        // per-scan1-block totals
__device__ int    g_is64;

static inline int cdiv(int a, int b) { return (a + b - 1) / b; }

// ---------------- cp.async + mma helpers -----------------------------------
__device__ __forceinline__ unsigned smem_u32p(const void* p) {
    return (unsigned)__cvta_generic_to_shared(p);
}
#define CP16(dst, src) asm volatile("cp.async.cg.shared.global [%0], [%1], 16;" :: "r"(dst), "l"(src))
#define CPCOMMIT()     asm volatile("cp.async.commit_group;")
#define CPWAIT0()      asm volatile("cp.async.wait_group 0;" ::: "memory")

__device__ __forceinline__ uint32_t f2tf32(float x) {
    uint32_t r;
    asm("cvt.rna.tf32.f32 %0, %1;" : "=r"(r) : "f"(x));
    return r;
}
__device__ __forceinline__ void mma_tf32(float* c, const uint32_t* a, const uint32_t* b) {
    asm("mma.sync.aligned.m16n8k8.row.col.f32.tf32.tf32.f32 "
        "{%0,%1,%2,%3},{%4,%5,%6,%7},{%8,%9},{%0,%1,%2,%3};"
        : "+f"(c[0]), "+f"(c[1]), "+f"(c[2]), "+f"(c[3])
        : "r"(a[0]), "r"(a[1]), "r"(a[2]), "r"(a[3]), "r"(b[0]), "r"(b[1]));
}

// ------------- init: zero counts + dtype probe (int64 vs int32) ------------
// Values are in [0, 50000): if stored as int64, every odd 32-bit word is 0.
__global__ void init_kernel(const unsigned int* __restrict__ w, int n) {
    int i = blockIdx.x * blockDim.x + threadIdx.x;
    if (i < n) g_counts[i] = 0;
    if (blockIdx.x == 0) {
        __shared__ int any;
        if (threadIdx.x == 0) any = 0;
        __syncthreads();
        int acc = 0;
        for (int j = threadIdx.x; j < 2048; j += blockDim.x) acc |= (int)w[2 * j + 1];
        atomicOr(&any, acc);
        __syncthreads();
        if (threadIdx.x == 0) g_is64 = (any == 0) ? 1 : 0;
    }
}

__global__ void count_dst_kernel(const void* __restrict__ ei, int E) {
    int i = blockIdx.x * blockDim.x + threadIdx.x;
    if (i >= E) return;
    int d = g_is64 ? (int)((const long long*)ei)[(size_t)E + i]
                   : ((const int*)ei)[E + i];
    atomicAdd(&g_counts[d], 1);
}

// --- multi-block scan, stage 1: per-block (1024 elems) exclusive scan ------
__global__ void __launch_bounds__(1024) scan1_kernel(int n) {
    __shared__ int warpsum[32];
    int i = blockIdx.x * 1024 + threadIdx.x;
    int lane = threadIdx.x & 31, w = threadIdx.x >> 5;
    int v = (i < n) ? g_counts[i] : 0;
    int x = v;
#pragma unroll
    for (int d = 1; d < 32; d <<= 1) {
        int t = __shfl_up_sync(0xffffffffu, x, d);
        if (lane >= d) x += t;
    }
    if (lane == 31) warpsum[w] = x;
    __syncthreads();
    if (w == 0) {
        int s = warpsum[lane];
#pragma unroll
        for (int d = 1; d < 32; d <<= 1) {
            int t = __shfl_up_sync(0xffffffffu, s, d);
            if (lane >= d) s += t;
        }
        warpsum[lane] = s;
    }
    __syncthreads();
    int incl = x + (w > 0 ? warpsum[w - 1] : 0);
    if (i < n) g_scanbuf[i] = incl - v;                 // exclusive within block
    if (threadIdx.x == 1023) g_blocksum[blockIdx.x] = incl;
}

// --- stage 2+3 merged: every block redundantly scans the <=64 block sums ---
__global__ void scan23_kernel(int nb, int n) {
    __shared__ int sh[64];
    __shared__ int pre[64];
    int t = threadIdx.x;
    if (t < 64) sh[t] = (t < nb) ? g_blocksum[t] : 0;
    __syncthreads();
    for (int d = 1; d < 64; d <<= 1) {
        int x = 0;
        if (t < 64 && t >= d) x = sh[t - d];
        __syncthreads();
        if (t < 64) sh[t] += x;
        __syncthreads();
    }
    if (t < 64) {
        int v = (t < nb) ? g_blocksum[t] : 0;
        pre[t] = sh[t] - v;                             // exclusive block offset
    }
    __syncthreads();
    int i = blockIdx.x * blockDim.x + t;
    if (i < n) {
        int off = pre[i >> 10] + g_scanbuf[i];
        g_indptr[i] = off;
        g_cursor[i] = off;
    }
    if (blockIdx.x == 0 && t == 0) g_indptr[n] = sh[63];
}

__global__ void scatter_kernel(const void* __restrict__ ei, int E) {
    int i = blockIdx.x * blockDim.x + threadIdx.x;
    if (i >= E) return;
    int s, d;
    if (g_is64) {
        s = (int)((const long long*)ei)[i];
        d = (int)((const long long*)ei)[(size_t)E + i];
    } else {
        s = ((const int*)ei)[i];
        d = ((const int*)ei)[E + i];
    }
    int pos = atomicAdd(&g_cursor[d], 1);
    g_csr[pos] = s;
}

// ---------------- tensor-core GEMM (3xTF32) + fused attention logits -------
// C[M x BN] = A[M x K] @ B[K x BN], fp32-grade accuracy via the error-
// compensated 3xTF32 scheme: big=tf32(v), small=tf32(v-big);
// D += Ab*Bb + Ab*Bs + As*Bb. 2-stage cp.async pipeline.
// 8 warps in a WM x WN grid (WN = BN/32), warp tile (BM/WM) x 32; each warp's
// 32 columns = one head, so the logit dot reduces over the 4-lane quad only.
// A smem [m][BK+4] and B smem [k][BN+8] are conflict-free for the m16n8k8
// fragment patterns. A rows clamped at M-1 (clamped rows never stored).
template <int BM, int BN, int HEADS>
__global__ void __launch_bounds__(256) gemm_logits_kernel(
    const float* __restrict__ A, const float* __restrict__ B,
    const float* __restrict__ aS, const float* __restrict__ aD,
    float* __restrict__ C, __half* __restrict__ Ch, int M, int K)
{
    constexpr int BK = 16;
    constexpr int WN = BN / 32;            // warps along N
    constexpr int WM = 8 / WN;             // warps along M
    constexpr int WTM = BM / WM;           // warp tile M (64 or 16)
    constexpr int MT = WTM / 16;           // m16 tiles per warp (4 or 1)
    constexpr int APAD = 4, BPAD = 8;
    constexpr int AE = BM * BK / (4 * 256);       // CP16 per thread for A
    constexpr int BF4 = BK * BN / 4;              // float4 slots in B tile
    constexpr int BI = (BF4 + 255) / 256;
    static_assert(WM * WN == 8 && MT * 16 * WM == BM, "tiling");

    __shared__ float As[2][BM][BK + APAD];
    __shared__ float Bs[2][BK][BN + BPAD];

    int tid  = threadIdx.x;
    int warp = tid >> 5, lane = tid & 31;
    int wm = warp / WN, wn = warp % WN;
    int g = lane >> 2, t = lane & 3;
    int m0 = blockIdx.x * BM;

    auto issue = [&](int tt) {
        int st = tt & 1;
        int k0 = tt * BK;
#pragma unroll
        for (int i = 0; i < AE; i++) {
            int f = tid + i * 256;
            int am = f >> 2;               // BK/4 = 4 groups per row
            int ak = (f & 3) * 4;
            int gm = m0 + am;
            if (gm > M - 1) gm = M - 1;    // clamp: clamped rows never stored
            CP16(smem_u32p(&As[st][am][ak]), &A[(size_t)gm * K + k0 + ak]);
        }
#pragma unroll
        for (int i = 0; i < BI; i++) {
            int f = tid + i * 256;
            if (BF4 % 256 == 0 || f < BF4) {
                int bk = f / (BN / 4);
                int bn = (f % (BN / 4)) * 4;
                CP16(smem_u32p(&Bs[st][bk][bn]), &B[(size_t)(k0 + bk) * BN + bn]);
            }
        }
        CPCOMMIT();
    };

    float acc[MT][4][4];
#pragma unroll
    for (int i = 0; i < MT; i++)
#pragma unroll
        for (int j = 0; j < 4; j++)
#pragma unroll
            for (int r = 0; r < 4; r++) acc[i][j][r] = 0.f;

    issue(0);
    int T = K / BK;
    for (int tt = 0; tt < T; tt++) {
        CPWAIT0();
        __syncthreads();
        if (tt + 1 < T) issue(tt + 1);
        int p = tt & 1;
#pragma unroll
        for (int ks = 0; ks < BK / 8; ks++) {
            int k8 = ks * 8;
            uint32_t Ab[MT][4], Asm[MT][4];
#pragma unroll
            for (int i = 0; i < MT; i++) {
                int r0 = wm * WTM + i * 16 + g;
                float v0 = As[p][r0][k8 + t];
                float v1 = As[p][r0 + 8][k8 + t];
                float v2 = As[p][r0][k8 + t + 4];
                float v3 = As[p][r0 + 8][k8 + t + 4];
                Ab[i][0] = f2tf32(v0); Asm[i][0] = f2tf32(v0 - __uint_as_float(Ab[i][0]));
                Ab[i][1] = f2tf32(v1); Asm[i][1] = f2tf32(v1 - __uint_as_float(Ab[i][1]));
                Ab[i][2] = f2tf32(v2); Asm[i][2] = f2tf32(v2 - __uint_as_float(Ab[i][2]));
                Ab[i][3] = f2tf32(v3); Asm[i][3] = f2tf32(v3 - __uint_as_float(Ab[i][3]));
            }
            uint32_t Bb[4][2], Bsm[4][2];
#pragma unroll
            for (int j = 0; j < 4; j++) {
                int col = wn * 32 + j * 8 + g;
                float v0 = Bs[p][k8 + t][col];
                float v1 = Bs[p][k8 + t + 4][col];
                Bb[j][0] = f2tf32(v0); Bsm[j][0] = f2tf32(v0 - __uint_as_float(Bb[j][0]));
                Bb[j][1] = f2tf32(v1); Bsm[j][1] = f2tf32(v1 - __uint_as_float(Bb[j][1]));
            }
#pragma unroll
            for (int i = 0; i < MT; i++)
#pragma unroll
                for (int j = 0; j < 4; j++) {
                    mma_tf32(acc[i][j], Ab[i], Bb[j]);
                    mma_tf32(acc[i][j], Ab[i], Bsm[j]);
                    mma_tf32(acc[i][j], Asm[i], Bb[j]);
                }
        }
    }

    // epilogue: C store (fp32 + fp16) + fused logits (quad reduce per row)
    int head = wn;                          // warp's 32 cols == one head
#pragma unroll
    for (int i = 0; i < MT; i++) {
        int r0 = m0 + wm * WTM + i * 16 + g;
        int r1 = r0 + 8;
        float pS0 = 0.f, pD0 = 0.f, pS1 = 0.f, pD1 = 0.f;
#pragma unroll
        for (int j = 0; j < 4; j++) {
            int c0 = wn * 32 + j * 8 + 2 * t;
            float aS0 = aS[c0], aS1 = aS[c0 + 1];
            float aD0 = aD[c0], aD1 = aD[c0 + 1];
            pS0 += acc[i][j][0] * aS0 + acc[i][j][1] * aS1;
            pD0 += acc[i][j][0] * aD0 + acc[i][j][1] * aD1;
            pS1 += acc[i][j][2] * aS0 + acc[i][j][3] * aS1;
            pD1 += acc[i][j][2] * aD0 + acc[i][j][3] * aD1;
            if (r0 < M) {
                *(float2*)&C[(size_t)r0 * BN + c0] =
                    make_float2(acc[i][j][0], acc[i][j][1]);
                __half2 hv = __floats2half2_rn(acc[i][j][0], acc[i][j][1]);
                *(__half2*)&Ch[(size_t)r0 * BN + c0] = hv;
            }
            if (r1 < M) {
                *(float2*)&C[(size_t)r1 * BN + c0] =
                    make_float2(acc[i][j][2], acc[i][j][3]);
                __half2 hv = __floats2half2_rn(acc[i][j][2], acc[i][j][3]);
                *(__half2*)&Ch[(size_t)r1 * BN + c0] = hv;
            }
        }
#pragma unroll
        for (int off = 1; off <= 2; off <<= 1) {
            pS0 += __shfl_xor_sync(0xffffffffu, pS0, off);
            pD0 += __shfl_xor_sync(0xffffffffu, pD0, off);
            pS1 += __shfl_xor_sync(0xffffffffu, pS1, off);
            pD1 += __shfl_xor_sync(0xffffffffu, pD1, off);
        }
        if (t == 0) {
            if (r0 < M) { g_als[r0 * HEADS + head] = pS0; g_ald[r0 * HEADS + head] = pD0; }
            if (r1 < M) { g_als[r1 * HEADS + head] = pS1; g_ald[r1 * HEADS + head] = pD1; }
        }
    }
}

// ---------------- GAT aggregation: one warp per destination node -----------
// Pass A max, pass B denom. Pass C: per 32-edge chunk, lanes compute all
// heads' alphas in parallel into smem, then the serial channel loop reads
// alpha/src from smem and only does the fp16 h-gather, 2-way unrolled.
// Self-loop analytic (fp32). Optional fused classifier head for layer 3.
template <int HEADS, int CH, bool ACT, bool FUSE_HEAD>
__global__ void __launch_bounds__(256) gat_agg_kernel(
    const float* __restrict__ h, const __half* __restrict__ hh,
    const float* __restrict__ bias,
    const float* __restrict__ Wc, const float* __restrict__ bc,
    float* __restrict__ out, int n)
{
    constexpr int F = HEADS * CH;
    constexpr int CL = F / 32;                 // channels per lane
    __shared__ float s_alpha[8][32 * HEADS];
    __shared__ int   s_src[8][32];
    int wslot = threadIdx.x >> 5;
    int warp = (blockIdx.x * blockDim.x + threadIdx.x) >> 5;
    int lane = threadIdx.x & 31;
    if (warp >= n) return;

    int start = g_indptr[warp], end = g_indptr[warp + 1];

    float aldv[HEADS], self_e[HEADS], m[HEADS];
    if constexpr (HEADS == 4) {
        float4 t = *(const float4*)&g_ald[warp * 4];
        aldv[0] = t.x; aldv[1] = t.y; aldv[2] = t.z; aldv[3] = t.w;
        float4 u = *(const float4*)&g_als[warp * 4];
        float sv[4] = {u.x, u.y, u.z, u.w};
#pragma unroll
        for (int hx = 0; hx < 4; hx++) {
            float e = sv[hx] + aldv[hx];
            e = e > 0.f ? e : 0.2f * e;
            self_e[hx] = e; m[hx] = e;
        }
    } else {
        aldv[0] = g_ald[warp];
        float e = g_als[warp] + aldv[0];
        e = e > 0.f ? e : 0.2f * e;
        self_e[0] = e; m[0] = e;
    }

    // pass A: max
    for (int eb = start; eb < end; eb += 32) {
        int e = eb + lane;
        if (e < end) {
            int s = g_csr[e];
            if constexpr (HEADS == 4) {
                float4 u = *(const float4*)&g_als[s * 4];
                float sv[4] = {u.x, u.y, u.z, u.w};
#pragma unroll
                for (int hx = 0; hx < 4; hx++) {
                    float x = sv[hx] + aldv[hx];
                    x = x > 0.f ? x : 0.2f * x;
                    m[hx] = fmaxf(m[hx], x);
                }
            } else {
                float x = g_als[s] + aldv[0];
                x = x > 0.f ? x : 0.2f * x;
                m[0] = fmaxf(m[0], x);
            }
        }
    }
#pragma unroll
    for (int hx = 0; hx < HEADS; hx++)
#pragma unroll
        for (int off = 16; off; off >>= 1)
            m[hx] = fmaxf(m[hx], __shfl_xor_sync(0xffffffffu, m[hx], off));

    // pass B: denom
    float den[HEADS];
#pragma unroll
    for (int hx = 0; hx < HEADS; hx++) den[hx] = 0.f;
    for (int eb = start; eb < end; eb += 32) {
        int e = eb + lane;
        if (e < end) {
            int s = g_csr[e];
            if constexpr (HEADS == 4) {
                float4 u = *(const float4*)&g_als[s * 4];
                float sv[4] = {u.x, u.y, u.z, u.w};
#pragma unroll
                for (int hx = 0; hx < 4; hx++) {
                    float x = sv[hx] + aldv[hx];
                    x = x > 0.f ? x : 0.2f * x;
                    den[hx] += __expf(x - m[hx]);
                }
            } else {
                float x = g_als[s] + aldv[0];
                x = x > 0.f ? x : 0.2f * x;
                den[0] += __expf(x - m[0]);
            }
        }
    }
#pragma unroll
    for (int hx = 0; hx < HEADS; hx++) {
#pragma unroll
        for (int off = 16; off; off >>= 1)
            den[hx] += __shfl_xor_sync(0xffffffffu, den[hx], off);
        den[hx] += __expf(self_e[hx] - m[hx]);
        den[hx] = 1.f / (den[hx] + 1e-16f);
    }

    // pass C: chunked. Lane owns channels [lane*CL, lane*CL+CL), one head.
    int myhead = (HEADS == 1) ? 0 : (lane >> 3);
    float acc[CL];
    {
        // self-loop message from the fp32 copy (largest alpha, keep exact)
        float alpha = __expf(self_e[myhead] - m[myhead]) * den[myhead];
        if constexpr (CL == 4) {
            float4 hv = *(const float4*)&h[(size_t)warp * F + lane * 4];
            acc[0] = hv.x * alpha; acc[1] = hv.y * alpha;
            acc[2] = hv.z * alpha; acc[3] = hv.w * alpha;
        } else {
            acc[0] = h[(size_t)warp * F + lane] * alpha;
        }
    }
    for (int cs = start; cs < end; cs += 32) {
        int cnt = min(32, end - cs);
        // parallel phase: alphas for up to 32 edges, all heads
        if (lane < cnt) {
            int s = g_csr[cs + lane];
            s_src[wslot][lane] = s;
            if constexpr (HEADS == 4) {
                float4 u = *(const float4*)&g_als[s * 4];
                float sv[4] = {u.x, u.y, u.z, u.w};
                float al[4];
#pragma unroll
                for (int hx = 0; hx < 4; hx++) {
                    float x = sv[hx] + aldv[hx];
                    x = x > 0.f ? x : 0.2f * x;
                    al[hx] = __expf(x - m[hx]) * den[hx];
                }
                *(float4*)&s_alpha[wslot][lane * 4] =
                    make_float4(al[0], al[1], al[2], al[3]);
            } else {
                float x = g_als[s] + aldv[0];
                x = x > 0.f ? x : 0.2f * x;
                s_alpha[wslot][lane] = __expf(x - m[0]) * den[0];
            }
        }
        __syncwarp();
        // serial phase: only the fp16 h-gather, 2-way unrolled
        int j = 0;
        for (; j + 1 < cnt; j += 2) {
            int s0 = s_src[wslot][j], s1 = s_src[wslot][j + 1];
            float a0, a1;
            if constexpr (HEADS == 4) {
                a0 = s_alpha[wslot][j * 4 + myhead];
                a1 = s_alpha[wslot][j * 4 + 4 + myhead];
            } else {
                a0 = s_alpha[wslot][j];
                a1 = s_alpha[wslot][j + 1];
            }
            if constexpr (CL == 4) {
                uint2 r0 = *(const uint2*)&hh[(size_t)s0 * F + lane * 4];
                uint2 r1 = *(const uint2*)&hh[(size_t)s1 * F + lane * 4];
                float2 f0a = __half22float2(*(__half2*)&r0.x);
                float2 f0b = __half22float2(*(__half2*)&r0.y);
                float2 f1a = __half22float2(*(__half2*)&r1.x);
                float2 f1b = __half22float2(*(__half2*)&r1.y);
                acc[0] += f0a.x * a0 + f1a.x * a1;
                acc[1] += f0a.y * a0 + f1a.y * a1;
                acc[2] += f0b.x * a0 + f1b.x * a1;
                acc[3] += f0b.y * a0 + f1b.y * a1;
            } else {
                acc[0] += __half2float(hh[(size_t)s0 * F + lane]) * a0
                        + __half2float(hh[(size_t)s1 * F + lane]) * a1;
            }
        }
        if (j < cnt) {
            int s0 = s_src[wslot][j];
            float a0 = (HEADS == 4) ? s_alpha[wslot][j * 4 + myhead]
                                    : s_alpha[wslot][j];
            if constexpr (CL == 4) {
                uint2 r0 = *(const uint2*)&hh[(size_t)s0 * F + lane * 4];
                float2 f0a = __half22float2(*(__half2*)&r0.x);
                float2 f0b = __half22float2(*(__half2*)&r0.y);
                acc[0] += f0a.x * a0; acc[1] += f0a.y * a0;
                acc[2] += f0b.x * a0; acc[3] += f0b.y * a0;
            } else {
                acc[0] += __half2float(hh[(size_t)s0 * F + lane]) * a0;
            }
        }
        __syncwarp();
    }

    if constexpr (FUSE_HEAD) {
        // layer 3: write link embedding + classifier logits directly to out
        float v = acc[0] + bias[lane];
        out[(size_t)n * 2 + (size_t)warp * 32 + lane] = v;
        float p0 = v * Wc[lane * 2 + 0];
        float p1 = v * Wc[lane * 2 + 1];
#pragma unroll
        for (int off = 16; off; off >>= 1) {
            p0 += __shfl_xor_sync(0xffffffffu, p0, off);
            p1 += __shfl_xor_sync(0xffffffffu, p1, off);
        }
        if (lane == 0) {
            out[(size_t)warp * 2 + 0] = p0 + bc[0];
            out[(size_t)warp * 2 + 1] = p1 + bc[1];
        }
    } else {
#pragma unroll
        for (int j = 0; j < CL; j++) {
            int c = lane * CL + j;
            float v = acc[j] + bias[c];
            if (ACT) v = v > 0.f ? v : (__expf(v) - 1.f);
            out[(size_t)warp * F + c] = v;
        }
    }
}

// ---------------- launch ----------------------------------------------------
extern "C" void kernel_launch(void* const* d_in, const int* in_sizes, int n_in,
                              void* d_out, int out_size)
{
    const float*  x    = (const float*)d_in[0];
    const void*   ei   = d_in[1];
    const float*  W1   = (const float*)d_in[2];
    const float*  a1s  = (const float*)d_in[3];
    const float*  a1d  = (const float*)d_in[4];
    const float*  b1   = (const float*)d_in[5];
    const float*  W2   = (const float*)d_in[6];
    const float*  a2s  = (const float*)d_in[7];
    const float*  a2d  = (const float*)d_in[8];
    const float*  b2   = (const float*)d_in[9];
    const float*  W3   = (const float*)d_in[10];
    const float*  a3s  = (const float*)d_in[11];
    const float*  a3d  = (const float*)d_in[12];
    const float*  b3   = (const float*)d_in[13];
    const float*  Wc   = (const float*)d_in[14];
    const float*  bc   = (const float*)d_in[15];
    float* out = (float*)d_out;

    int N = in_sizes[0] / FDIM;     // 50000
    int E = in_sizes[1] / 2;        // 800000 (element count same for i32/i64)

    float  *lin, *feat;
    __half *linh;
    cudaGetSymbolAddress((void**)&lin,  g_lin);
    cudaGetSymbolAddress((void**)&linh, g_linh);
    cudaGetSymbolAddress((void**)&feat, g_feat);

    // --- CSR by destination (rebuilt every replay; deterministic work) ---
    init_kernel<<<cdiv(N, 256), 256>>>((const unsigned int*)ei, N);
    count_dst_kernel<<<cdiv(E, 256), 256>>>(ei, E);
    int nb = cdiv(N, 1024);
    scan1_kernel<<<nb, 1024>>>(N);
    scan23_kernel<<<cdiv(N, 256), 256>>>(nb, N);
    scatter_kernel<<<cdiv(E, 256), 256>>>(ei, E);

    // --- layer 1: x[128] -> 128, 4 heads, ELU ---
    gemm_logits_kernel<128, 128, 4><<<cdiv(N, 128), 256>>>(
        x, W1, a1s, a1d, lin, linh, N, 128);
    gat_agg_kernel<4, 32, true, false><<<cdiv(N * 32, 256), 256>>>(
        lin, linh, b1, nullptr, nullptr, feat, N);

    // --- layer 2: 128 -> 128, 4 heads, ELU ---
    gemm_logits_kernel<128, 128, 4><<<cdiv(N, 128), 256>>>(
        feat, W2, a2s, a2d, lin, linh, N, 128);
    gat_agg_kernel<4, 32, true, false><<<cdiv(N * 32, 256), 256>>>(
        lin, linh, b2, nullptr, nullptr, feat, N);

    // --- layer 3: 128 -> 32, 1 head, no activation; fused classifier head ---
    gemm_logits_kernel<128, 32, 1><<<cdiv(N, 128), 256>>>(
        feat, W3, a3s, a3d, lin, linh, N, 128);
    gat_agg_kernel<1, 32, false, true><<<cdiv(N * 32, 256), 256>>>(
        lin, linh, b3, Wc, bc, out, N);
}